// round 2
// baseline (speedup 1.0000x reference)
#include <cuda_runtime.h>
#include <math.h>

#define BSZ 2
#define SEQ 2048
#define DMODEL 2048
#define NHEADS 16
#define HDIM 128
#define NROWS (BSZ*SEQ)   // 4096

// Scratch (allocation-free rule: __device__ globals)
__device__ float g_q[BSZ*NHEADS*SEQ*HDIM];
__device__ float g_k[BSZ*NHEADS*SEQ*HDIM];
__device__ float g_v[BSZ*NHEADS*SEQ*HDIM];
__device__ float g_ctx[(size_t)BSZ*SEQ*DMODEL];

// ---------------------------------------------------------------------------
// NT GEMM: C[M,N] = A[M,K] @ W[N,K]^T      M=4096, N=2048, K=2048
// BM=BN=128, BK=16, 256 threads, 8x8 microtile.
// MODE 0: z selects Wq/Wk/Wv, epilogue scatters to [b,h,t,dh] (g_q/g_k/g_v)
// MODE 1: A = g_ctx, single W, adds bias, writes plain row-major to Cplain
// ---------------------------------------------------------------------------
template<int MODE>
__global__ void __launch_bounds__(256) gemm_nt_kernel(
    const float* __restrict__ Ain,
    const float* __restrict__ W0,
    const float* __restrict__ W1,
    const float* __restrict__ W2,
    const float* __restrict__ bias,
    float* __restrict__ Cplain)
{
    __shared__ float As[16][132];
    __shared__ float Bs[16][132];

    const float* A;
    const float* W;
    float* dstQKV = nullptr;
    if (MODE == 0) {
        A = Ain;
        W = (blockIdx.z == 0) ? W0 : (blockIdx.z == 1 ? W1 : W2);
        dstQKV = (blockIdx.z == 0) ? g_q : (blockIdx.z == 1 ? g_k : g_v);
    } else {
        A = g_ctx;
        W = W0;
    }

    int tid = threadIdx.x;
    int tx = tid & 15;
    int ty = tid >> 4;
    int rowBase = blockIdx.y * 128;
    int colBase = blockIdx.x * 128;

    float acc[8][8];
    #pragma unroll
    for (int i = 0; i < 8; i++)
        #pragma unroll
        for (int j = 0; j < 8; j++) acc[i][j] = 0.f;

    for (int k0 = 0; k0 < DMODEL; k0 += 16) {
        #pragma unroll
        for (int i = 0; i < 2; i++) {
            int idx = tid * 2 + i;          // 0..511
            int r = idx >> 2;               // 0..127
            int kq = (idx & 3) << 2;        // 0,4,8,12
            float4 va = *(const float4*)(A + (size_t)(rowBase + r) * DMODEL + k0 + kq);
            As[kq+0][r] = va.x; As[kq+1][r] = va.y; As[kq+2][r] = va.z; As[kq+3][r] = va.w;
            float4 vb = *(const float4*)(W + (size_t)(colBase + r) * DMODEL + k0 + kq);
            Bs[kq+0][r] = vb.x; Bs[kq+1][r] = vb.y; Bs[kq+2][r] = vb.z; Bs[kq+3][r] = vb.w;
        }
        __syncthreads();

        #pragma unroll
        for (int kk = 0; kk < 16; kk++) {
            float4 a0 = *(const float4*)&As[kk][ty*8];
            float4 a1 = *(const float4*)&As[kk][ty*8+4];
            float4 b0 = *(const float4*)&Bs[kk][tx*8];
            float4 b1 = *(const float4*)&Bs[kk][tx*8+4];
            float ra[8] = {a0.x,a0.y,a0.z,a0.w,a1.x,a1.y,a1.z,a1.w};
            float rb[8] = {b0.x,b0.y,b0.z,b0.w,b1.x,b1.y,b1.z,b1.w};
            #pragma unroll
            for (int i = 0; i < 8; i++)
                #pragma unroll
                for (int j = 0; j < 8; j++)
                    acc[i][j] += ra[i] * rb[j];
        }
        __syncthreads();
    }

    if (MODE == 0) {
        #pragma unroll
        for (int i = 0; i < 8; i++) {
            int m = rowBase + ty*8 + i;
            int b = m >> 11;
            int t = m & (SEQ-1);
            #pragma unroll
            for (int j = 0; j < 8; j++) {
                int n = colBase + tx*8 + j;
                int h = n >> 7;
                int dh = n & (HDIM-1);
                dstQKV[(((size_t)(b*NHEADS + h) * SEQ + t) << 7) + dh] = acc[i][j];
            }
        }
    } else {
        #pragma unroll
        for (int i = 0; i < 8; i++) {
            int m = rowBase + ty*8 + i;
            #pragma unroll
            for (int j = 0; j < 8; j++) {
                int n = colBase + tx*8 + j;
                Cplain[(size_t)m * DMODEL + n] = acc[i][j] + bias[n];
            }
        }
    }
}

// ---------------------------------------------------------------------------
// RoPE in-place on g_q / g_k. Block (64,4): 4 rows per block, 64 pairs each.
// out[d]    = v[2d]*cos - v[2d+1]*sin
// out[64+d] = v[2d]*sin + v[2d+1]*cos       (d in [0,64))
// ---------------------------------------------------------------------------
__global__ void rope_kernel(const float* __restrict__ theta)
{
    int d = threadIdx.x;                        // 0..63
    int t = blockIdx.x * 4 + threadIdx.y;       // 0..2047
    int bh = blockIdx.y;                        // 0..31
    float* buf = blockIdx.z ? g_k : g_q;
    float* row = buf + ((size_t)bh * SEQ + t) * HDIM;

    float ve = row[2*d];
    float vo = row[2*d+1];
    float f = (float)t * theta[d];
    float s, c;
    sincosf(f, &s, &c);
    __syncthreads();                            // all reads before any write
    row[d]      = ve * c - vo * s;
    row[64 + d] = ve * s + vo * c;
}

// ---------------------------------------------------------------------------
// Flash attention, causal. One block per (q-tile 64 rows, bh). 256 threads.
// Thread (ty,tx): 4 q-rows (ty*4..+4), 4 score cols (tx*4..+4), 8 o-cols (tx*8..+8)
// SMEM rows padded to 132 floats to avoid bank conflicts.
// ---------------------------------------------------------------------------
#define ATTN_SMEM_FLOATS (3*64*132 + 64*68 + 2*64*16 + 128)

__global__ void __launch_bounds__(256) attn_kernel()
{
    extern __shared__ float sm[];
    float* Qs   = sm;                    // 64*132
    float* Ks   = Qs + 64*132;
    float* Vs   = Ks + 64*132;
    float* Ps   = Vs + 64*132;           // 64*68
    float* redm = Ps + 64*68;            // 64*16
    float* reds = redm + 64*16;          // 64*16
    float* mrow = reds + 64*16;          // 64
    float* lrow = mrow + 64;             // 64

    int tid = threadIdx.x;
    int tx = tid & 15;
    int ty = tid >> 4;
    int qt = blockIdx.x;
    int bh = blockIdx.y;
    const float scale = 0.08838834764831845f;    // 1/sqrt(128)
    size_t base = (size_t)bh * SEQ * HDIM;
    int qs = qt * 64;

    // Load Q tile
    #pragma unroll
    for (int p = 0; p < 8; p++) {
        int idx = tid + p * 256;                 // 0..2047
        int r = idx >> 5;
        int c = (idx & 31) << 2;
        *(float4*)&Qs[r*132 + c] = *(const float4*)(g_q + base + (size_t)(qs + r) * HDIM + c);
    }
    if (tid < 64) { mrow[tid] = -3.0e38f; lrow[tid] = 0.f; }
    __syncthreads();

    float o[4][8];
    #pragma unroll
    for (int i = 0; i < 4; i++)
        #pragma unroll
        for (int j = 0; j < 8; j++) o[i][j] = 0.f;

    for (int kt = 0; kt <= qt; kt++) {
        int ks = kt * 64;
        #pragma unroll
        for (int p = 0; p < 8; p++) {
            int idx = tid + p * 256;
            int r = idx >> 5;
            int c = (idx & 31) << 2;
            *(float4*)&Ks[r*132 + c] = *(const float4*)(g_k + base + (size_t)(ks + r) * HDIM + c);
            *(float4*)&Vs[r*132 + c] = *(const float4*)(g_v + base + (size_t)(ks + r) * HDIM + c);
        }
        __syncthreads();

        // S = Q K^T (4x4 microtile), masked + scaled
        float s[4][4];
        #pragma unroll
        for (int i = 0; i < 4; i++)
            #pragma unroll
            for (int j = 0; j < 4; j++) s[i][j] = 0.f;

        #pragma unroll 4
        for (int d4 = 0; d4 < HDIM; d4 += 4) {
            float4 qv[4], kv[4];
            #pragma unroll
            for (int i = 0; i < 4; i++) qv[i] = *(const float4*)&Qs[(ty*4+i)*132 + d4];
            #pragma unroll
            for (int j = 0; j < 4; j++) kv[j] = *(const float4*)&Ks[(tx*4+j)*132 + d4];
            #pragma unroll
            for (int i = 0; i < 4; i++)
                #pragma unroll
                for (int j = 0; j < 4; j++)
                    s[i][j] += qv[i].x*kv[j].x + qv[i].y*kv[j].y + qv[i].z*kv[j].z + qv[i].w*kv[j].w;
        }

        float mold[4];
        #pragma unroll
        for (int i = 0; i < 4; i++) {
            int qr = ty*4 + i;
            int qpos = qs + qr;
            float mx = -3.0e38f;
            #pragma unroll
            for (int j = 0; j < 4; j++) {
                int kpos = ks + tx*4 + j;
                float v = (kpos <= qpos) ? s[i][j] * scale : -3.0e38f;
                s[i][j] = v;
                mx = fmaxf(mx, v);
            }
            redm[qr*16 + tx] = mx;
            mold[i] = mrow[qr];
        }
        __syncthreads();

        float newm[4], fac[4];
        #pragma unroll
        for (int i = 0; i < 4; i++) {
            int qr = ty*4 + i;
            float mx = mold[i];
            #pragma unroll
            for (int u = 0; u < 16; u++) mx = fmaxf(mx, redm[qr*16 + u]);
            newm[i] = mx;
            fac[i] = __expf(mold[i] - mx);
            float psum = 0.f;
            #pragma unroll
            for (int j = 0; j < 4; j++) {
                float p = __expf(s[i][j] - mx);
                Ps[qr*68 + tx*4 + j] = p;
                psum += p;
            }
            reds[qr*16 + tx] = psum;
            #pragma unroll
            for (int j = 0; j < 8; j++) o[i][j] *= fac[i];
        }
        __syncthreads();

        if (tx == 0) {
            #pragma unroll
            for (int i = 0; i < 4; i++) {
                int qr = ty*4 + i;
                float ssum = 0.f;
                #pragma unroll
                for (int u = 0; u < 16; u++) ssum += reds[qr*16 + u];
                lrow[qr] = lrow[qr] * fac[i] + ssum;
                mrow[qr] = newm[i];
            }
        }

        // O += P @ V
        #pragma unroll 2
        for (int kc = 0; kc < 64; kc += 4) {
            float4 va[4], vb[4];
            #pragma unroll
            for (int r = 0; r < 4; r++) {
                va[r] = *(const float4*)&Vs[(kc+r)*132 + tx*8];
                vb[r] = *(const float4*)&Vs[(kc+r)*132 + tx*8 + 4];
            }
            #pragma unroll
            for (int i = 0; i < 4; i++) {
                float4 p = *(const float4*)&Ps[(ty*4+i)*68 + kc];
                o[i][0] += p.x*va[0].x + p.y*va[1].x + p.z*va[2].x + p.w*va[3].x;
                o[i][1] += p.x*va[0].y + p.y*va[1].y + p.z*va[2].y + p.w*va[3].y;
                o[i][2] += p.x*va[0].z + p.y*va[1].z + p.z*va[2].z + p.w*va[3].z;
                o[i][3] += p.x*va[0].w + p.y*va[1].w + p.z*va[2].w + p.w*va[3].w;
                o[i][4] += p.x*vb[0].x + p.y*vb[1].x + p.z*vb[2].x + p.w*vb[3].x;
                o[i][5] += p.x*vb[0].y + p.y*vb[1].y + p.z*vb[2].y + p.w*vb[3].y;
                o[i][6] += p.x*vb[0].z + p.y*vb[1].z + p.z*vb[2].z + p.w*vb[3].z;
                o[i][7] += p.x*vb[0].w + p.y*vb[1].w + p.z*vb[2].w + p.w*vb[3].w;
            }
        }
        __syncthreads();
    }

    // Epilogue: write ctx in [b, t, h*128+dh] so out-proj is a plain GEMM
    int b = bh >> 4;
    int h = bh & 15;
    #pragma unroll
    for (int i = 0; i < 4; i++) {
        int qr = ty*4 + i;
        float inv = 1.f / lrow[qr];
        float* dst = g_ctx + ((size_t)(b*SEQ + qs + qr) * DMODEL) + h*HDIM + tx*8;
        float4 r0 = make_float4(o[i][0]*inv, o[i][1]*inv, o[i][2]*inv, o[i][3]*inv);
        float4 r1 = make_float4(o[i][4]*inv, o[i][5]*inv, o[i][6]*inv, o[i][7]*inv);
        *(float4*)dst = r0;
        *(float4*)(dst+4) = r1;
    }
}

// ---------------------------------------------------------------------------
extern "C" void kernel_launch(void* const* d_in, const int* in_sizes, int n_in,
                              void* d_out, int out_size)
{
    const float* x     = (const float*)d_in[0];
    const float* Wq    = (const float*)d_in[1];
    const float* Wk    = (const float*)d_in[2];
    const float* Wv    = (const float*)d_in[3];
    const float* Wo    = (const float*)d_in[4];
    const float* bo    = (const float*)d_in[5];
    const float* theta = (const float*)d_in[6];
    float* out = (float*)d_out;

    // 1. QKV projections (z = 0,1,2 -> Wq,Wk,Wv), scatter to [b,h,t,dh]
    gemm_nt_kernel<0><<<dim3(DMODEL/128, NROWS/128, 3), 256>>>(x, Wq, Wk, Wv, nullptr, nullptr);

    // 2. RoPE on q and k
    rope_kernel<<<dim3(SEQ/4, BSZ*NHEADS, 2), dim3(64, 4)>>>(theta);

    // 3. Causal flash attention
    const int smem_bytes = ATTN_SMEM_FLOATS * (int)sizeof(float);
    cudaFuncSetAttribute(attn_kernel, cudaFuncAttributeMaxDynamicSharedMemorySize, smem_bytes);
    attn_kernel<<<dim3(SEQ/64, BSZ*NHEADS), 256, smem_bytes>>>();

    // 4. Output projection + bias
    gemm_nt_kernel<1><<<dim3(DMODEL/128, NROWS/128, 1), 256>>>(nullptr, Wo, nullptr, nullptr, bo, out);
}

// round 3
// speedup vs baseline: 1.4909x; 1.4909x over previous
#include <cuda_runtime.h>
#include <math.h>
#include <stdint.h>

#define BSZ 2
#define SEQ 2048
#define DMODEL 2048
#define NHEADS 16
#define HDIM 128
#define NROWS (BSZ*SEQ)   // 4096

// Scratch (allocation-free rule: __device__ globals)
__device__ float g_q[BSZ*NHEADS*SEQ*HDIM];
__device__ float g_k[BSZ*NHEADS*SEQ*HDIM];
__device__ float g_v[BSZ*NHEADS*SEQ*HDIM];
__device__ float g_ctx[(size_t)BSZ*SEQ*DMODEL];

__device__ __forceinline__ uint32_t f32_to_tf32(float f) {
    uint32_t r;
    asm("cvt.rna.tf32.f32 %0, %1;" : "=r"(r) : "f"(f));
    return r;
}

__device__ __forceinline__ void mma_tf32_16x8x8(float c[4], const uint32_t a[4], const uint32_t b[2]) {
    asm volatile(
        "mma.sync.aligned.m16n8k8.row.col.f32.tf32.tf32.f32 "
        "{%0,%1,%2,%3}, {%4,%5,%6,%7}, {%8,%9}, {%0,%1,%2,%3};"
        : "+f"(c[0]), "+f"(c[1]), "+f"(c[2]), "+f"(c[3])
        : "r"(a[0]), "r"(a[1]), "r"(a[2]), "r"(a[3]), "r"(b[0]), "r"(b[1]));
}

// ---------------------------------------------------------------------------
// tf32 NT GEMM: C[M,N] = A[M,K] @ W[N,K]^T    M=4096, N=2048, K=2048
// BM=BN=128, BK=32, 256 threads (8 warps, 2x4), warp tile 64x32.
// MODE 0: z selects Wq/Wk/Wv, epilogue scatters to [b,h,t,dh]
// MODE 1: A = g_ctx, adds bias, writes row-major to Cplain
// ---------------------------------------------------------------------------
template<int MODE>
__global__ void __launch_bounds__(256) gemm_tf32_kernel(
    const float* __restrict__ Ain,
    const float* __restrict__ W0,
    const float* __restrict__ W1,
    const float* __restrict__ W2,
    const float* __restrict__ bias,
    float* __restrict__ Cplain)
{
    __shared__ uint32_t As[32][136];   // [k][m], tf32 bits
    __shared__ uint32_t Bs[32][136];   // [k][n], tf32 bits

    const float* A;
    const float* W;
    float* dstQKV = nullptr;
    if (MODE == 0) {
        A = Ain;
        W = (blockIdx.z == 0) ? W0 : (blockIdx.z == 1 ? W1 : W2);
        dstQKV = (blockIdx.z == 0) ? g_q : (blockIdx.z == 1 ? g_k : g_v);
    } else {
        A = g_ctx;
        W = W0;
    }

    const int tid  = threadIdx.x;
    const int lane = tid & 31;
    const int wrp  = tid >> 5;
    const int wm   = (wrp >> 2) * 64;   // warp row offset in tile
    const int wn   = (wrp & 3) * 32;    // warp col offset in tile
    const int g    = lane >> 2;         // group id 0..7
    const int tg   = lane & 3;          // thread-in-group 0..3

    const int rowBase = blockIdx.y * 128;
    const int colBase = blockIdx.x * 128;

    float acc[4][4][4];
    #pragma unroll
    for (int i = 0; i < 4; i++)
        #pragma unroll
        for (int j = 0; j < 4; j++)
            #pragma unroll
            for (int c = 0; c < 4; c++) acc[i][j][c] = 0.f;

    for (int k0 = 0; k0 < DMODEL; k0 += 32) {
        // Load + transpose + convert: 1024 float4 per operand, 4 per thread
        #pragma unroll
        for (int p = 0; p < 4; p++) {
            int idx = tid + p * 256;         // 0..1023
            int r  = idx >> 3;               // 0..127 (m or n)
            int kq = (idx & 7) << 2;         // 0,4,...,28
            float4 va = *(const float4*)(A + (size_t)(rowBase + r) * DMODEL + k0 + kq);
            As[kq+0][r] = f32_to_tf32(va.x);
            As[kq+1][r] = f32_to_tf32(va.y);
            As[kq+2][r] = f32_to_tf32(va.z);
            As[kq+3][r] = f32_to_tf32(va.w);
            float4 vb = *(const float4*)(W + (size_t)(colBase + r) * DMODEL + k0 + kq);
            Bs[kq+0][r] = f32_to_tf32(vb.x);
            Bs[kq+1][r] = f32_to_tf32(vb.y);
            Bs[kq+2][r] = f32_to_tf32(vb.z);
            Bs[kq+3][r] = f32_to_tf32(vb.w);
        }
        __syncthreads();

        #pragma unroll
        for (int kk = 0; kk < 4; kk++) {
            const int kb = kk * 8;
            uint32_t af[4][4], bf[4][2];
            #pragma unroll
            for (int i = 0; i < 4; i++) {
                int row = wm + i * 16 + g;
                af[i][0] = As[kb + tg    ][row];
                af[i][1] = As[kb + tg    ][row + 8];
                af[i][2] = As[kb + tg + 4][row];
                af[i][3] = As[kb + tg + 4][row + 8];
            }
            #pragma unroll
            for (int j = 0; j < 4; j++) {
                int col = wn + j * 8 + g;
                bf[j][0] = Bs[kb + tg    ][col];
                bf[j][1] = Bs[kb + tg + 4][col];
            }
            #pragma unroll
            for (int i = 0; i < 4; i++)
                #pragma unroll
                for (int j = 0; j < 4; j++)
                    mma_tf32_16x8x8(acc[i][j], af[i], bf[j]);
        }
        __syncthreads();
    }

    if (MODE == 0) {
        #pragma unroll
        for (int i = 0; i < 4; i++) {
            #pragma unroll
            for (int cc = 0; cc < 2; cc++) {
                int m = rowBase + wm + i * 16 + g + cc * 8;
                int b = m >> 11;
                int t = m & (SEQ - 1);
                size_t rowoff = ((size_t)(b * NHEADS) * SEQ + t) << 7;  // + h*SEQ*128 later
                #pragma unroll
                for (int j = 0; j < 4; j++) {
                    int n0 = colBase + wn + j * 8 + tg * 2;
                    int h  = n0 >> 7;
                    int dh = n0 & (HDIM - 1);
                    float* dst = dstQKV + rowoff + (((size_t)h * SEQ) << 7) + dh;
                    dst[0] = acc[i][j][cc * 2 + 0];
                    dst[1] = acc[i][j][cc * 2 + 1];
                }
            }
        }
    } else {
        #pragma unroll
        for (int i = 0; i < 4; i++) {
            #pragma unroll
            for (int cc = 0; cc < 2; cc++) {
                int m = rowBase + wm + i * 16 + g + cc * 8;
                #pragma unroll
                for (int j = 0; j < 4; j++) {
                    int n0 = colBase + wn + j * 8 + tg * 2;
                    float2 v;
                    v.x = acc[i][j][cc * 2 + 0] + bias[n0];
                    v.y = acc[i][j][cc * 2 + 1] + bias[n0 + 1];
                    *(float2*)(Cplain + (size_t)m * DMODEL + n0) = v;
                }
            }
        }
    }
}

// ---------------------------------------------------------------------------
// RoPE in-place on g_q / g_k. Block (64,4): 4 rows per block, 64 pairs each.
// ---------------------------------------------------------------------------
__global__ void rope_kernel(const float* __restrict__ theta)
{
    int d = threadIdx.x;                        // 0..63
    int t = blockIdx.x * 4 + threadIdx.y;       // 0..2047
    int bh = blockIdx.y;                        // 0..31
    float* buf = blockIdx.z ? g_k : g_q;
    float* row = buf + ((size_t)bh * SEQ + t) * HDIM;

    float ve = row[2*d];
    float vo = row[2*d+1];
    float f = (float)t * theta[d];
    float s, c;
    sincosf(f, &s, &c);
    __syncthreads();                            // all reads before any write
    row[d]      = ve * c - vo * s;
    row[64 + d] = ve * s + vo * c;
}

// ---------------------------------------------------------------------------
// Flash attention, causal (fp32, unchanged from R2 baseline).
// ---------------------------------------------------------------------------
#define ATTN_SMEM_FLOATS (3*64*132 + 64*68 + 2*64*16 + 128)

__global__ void __launch_bounds__(256) attn_kernel()
{
    extern __shared__ float sm[];
    float* Qs   = sm;                    // 64*132
    float* Ks   = Qs + 64*132;
    float* Vs   = Ks + 64*132;
    float* Ps   = Vs + 64*132;           // 64*68
    float* redm = Ps + 64*68;            // 64*16
    float* reds = redm + 64*16;          // 64*16
    float* mrow = reds + 64*16;          // 64
    float* lrow = mrow + 64;             // 64

    int tid = threadIdx.x;
    int tx = tid & 15;
    int ty = tid >> 4;
    int qt = blockIdx.x;
    int bh = blockIdx.y;
    const float scale = 0.08838834764831845f;    // 1/sqrt(128)
    size_t base = (size_t)bh * SEQ * HDIM;
    int qs = qt * 64;

    #pragma unroll
    for (int p = 0; p < 8; p++) {
        int idx = tid + p * 256;                 // 0..2047
        int r = idx >> 5;
        int c = (idx & 31) << 2;
        *(float4*)&Qs[r*132 + c] = *(const float4*)(g_q + base + (size_t)(qs + r) * HDIM + c);
    }
    if (tid < 64) { mrow[tid] = -3.0e38f; lrow[tid] = 0.f; }
    __syncthreads();

    float o[4][8];
    #pragma unroll
    for (int i = 0; i < 4; i++)
        #pragma unroll
        for (int j = 0; j < 8; j++) o[i][j] = 0.f;

    for (int kt = 0; kt <= qt; kt++) {
        int ks = kt * 64;
        #pragma unroll
        for (int p = 0; p < 8; p++) {
            int idx = tid + p * 256;
            int r = idx >> 5;
            int c = (idx & 31) << 2;
            *(float4*)&Ks[r*132 + c] = *(const float4*)(g_k + base + (size_t)(ks + r) * HDIM + c);
            *(float4*)&Vs[r*132 + c] = *(const float4*)(g_v + base + (size_t)(ks + r) * HDIM + c);
        }
        __syncthreads();

        float s[4][4];
        #pragma unroll
        for (int i = 0; i < 4; i++)
            #pragma unroll
            for (int j = 0; j < 4; j++) s[i][j] = 0.f;

        #pragma unroll 4
        for (int d4 = 0; d4 < HDIM; d4 += 4) {
            float4 qv[4], kv[4];
            #pragma unroll
            for (int i = 0; i < 4; i++) qv[i] = *(const float4*)&Qs[(ty*4+i)*132 + d4];
            #pragma unroll
            for (int j = 0; j < 4; j++) kv[j] = *(const float4*)&Ks[(tx*4+j)*132 + d4];
            #pragma unroll
            for (int i = 0; i < 4; i++)
                #pragma unroll
                for (int j = 0; j < 4; j++)
                    s[i][j] += qv[i].x*kv[j].x + qv[i].y*kv[j].y + qv[i].z*kv[j].z + qv[i].w*kv[j].w;
        }

        float mold[4];
        #pragma unroll
        for (int i = 0; i < 4; i++) {
            int qr = ty*4 + i;
            int qpos = qs + qr;
            float mx = -3.0e38f;
            #pragma unroll
            for (int j = 0; j < 4; j++) {
                int kpos = ks + tx*4 + j;
                float v = (kpos <= qpos) ? s[i][j] * scale : -3.0e38f;
                s[i][j] = v;
                mx = fmaxf(mx, v);
            }
            redm[qr*16 + tx] = mx;
            mold[i] = mrow[qr];
        }
        __syncthreads();

        float newm[4], fac[4];
        #pragma unroll
        for (int i = 0; i < 4; i++) {
            int qr = ty*4 + i;
            float mx = mold[i];
            #pragma unroll
            for (int u = 0; u < 16; u++) mx = fmaxf(mx, redm[qr*16 + u]);
            newm[i] = mx;
            fac[i] = __expf(mold[i] - mx);
            float psum = 0.f;
            #pragma unroll
            for (int j = 0; j < 4; j++) {
                float p = __expf(s[i][j] - mx);
                Ps[qr*68 + tx*4 + j] = p;
                psum += p;
            }
            reds[qr*16 + tx] = psum;
            #pragma unroll
            for (int j = 0; j < 8; j++) o[i][j] *= fac[i];
        }
        __syncthreads();

        if (tx == 0) {
            #pragma unroll
            for (int i = 0; i < 4; i++) {
                int qr = ty*4 + i;
                float ssum = 0.f;
                #pragma unroll
                for (int u = 0; u < 16; u++) ssum += reds[qr*16 + u];
                lrow[qr] = lrow[qr] * fac[i] + ssum;
                mrow[qr] = newm[i];
            }
        }

        #pragma unroll 2
        for (int kc = 0; kc < 64; kc += 4) {
            float4 va[4], vb[4];
            #pragma unroll
            for (int r = 0; r < 4; r++) {
                va[r] = *(const float4*)&Vs[(kc+r)*132 + tx*8];
                vb[r] = *(const float4*)&Vs[(kc+r)*132 + tx*8 + 4];
            }
            #pragma unroll
            for (int i = 0; i < 4; i++) {
                float4 p = *(const float4*)&Ps[(ty*4+i)*68 + kc];
                o[i][0] += p.x*va[0].x + p.y*va[1].x + p.z*va[2].x + p.w*va[3].x;
                o[i][1] += p.x*va[0].y + p.y*va[1].y + p.z*va[2].y + p.w*va[3].y;
                o[i][2] += p.x*va[0].z + p.y*va[1].z + p.z*va[2].z + p.w*va[3].z;
                o[i][3] += p.x*va[0].w + p.y*va[1].w + p.z*va[2].w + p.w*va[3].w;
                o[i][4] += p.x*vb[0].x + p.y*vb[1].x + p.z*vb[2].x + p.w*vb[3].x;
                o[i][5] += p.x*vb[0].y + p.y*vb[1].y + p.z*vb[2].y + p.w*vb[3].y;
                o[i][6] += p.x*vb[0].z + p.y*vb[1].z + p.z*vb[2].z + p.w*vb[3].z;
                o[i][7] += p.x*vb[0].w + p.y*vb[1].w + p.z*vb[2].w + p.w*vb[3].w;
            }
        }
        __syncthreads();
    }

    int b = bh >> 4;
    int h = bh & 15;
    #pragma unroll
    for (int i = 0; i < 4; i++) {
        int qr = ty*4 + i;
        float inv = 1.f / lrow[qr];
        float* dst = g_ctx + ((size_t)(b*SEQ + qs + qr) * DMODEL) + h*HDIM + tx*8;
        float4 r0 = make_float4(o[i][0]*inv, o[i][1]*inv, o[i][2]*inv, o[i][3]*inv);
        float4 r1 = make_float4(o[i][4]*inv, o[i][5]*inv, o[i][6]*inv, o[i][7]*inv);
        *(float4*)dst = r0;
        *(float4*)(dst+4) = r1;
    }
}

// ---------------------------------------------------------------------------
extern "C" void kernel_launch(void* const* d_in, const int* in_sizes, int n_in,
                              void* d_out, int out_size)
{
    const float* x     = (const float*)d_in[0];
    const float* Wq    = (const float*)d_in[1];
    const float* Wk    = (const float*)d_in[2];
    const float* Wv    = (const float*)d_in[3];
    const float* Wo    = (const float*)d_in[4];
    const float* bo    = (const float*)d_in[5];
    const float* theta = (const float*)d_in[6];
    float* out = (float*)d_out;

    // 1. QKV projections (tf32 tensor cores), scatter to [b,h,t,dh]
    gemm_tf32_kernel<0><<<dim3(DMODEL/128, NROWS/128, 3), 256>>>(x, Wq, Wk, Wv, nullptr, nullptr);

    // 2. RoPE on q and k
    rope_kernel<<<dim3(SEQ/4, BSZ*NHEADS, 2), dim3(64, 4)>>>(theta);

    // 3. Causal flash attention
    const int smem_bytes = ATTN_SMEM_FLOATS * (int)sizeof(float);
    cudaFuncSetAttribute(attn_kernel, cudaFuncAttributeMaxDynamicSharedMemorySize, smem_bytes);
    attn_kernel<<<dim3(SEQ/64, BSZ*NHEADS), 256, smem_bytes>>>();

    // 4. Output projection + bias (tf32 tensor cores)
    gemm_tf32_kernel<1><<<dim3(DMODEL/128, NROWS/128, 1), 256>>>(nullptr, Wo, nullptr, nullptr, bo, out);
}

// round 4
// speedup vs baseline: 2.5463x; 1.7079x over previous
#include <cuda_runtime.h>
#include <cuda_bf16.h>
#include <math.h>
#include <stdint.h>

#define BSZ 2
#define SEQ 2048
#define DMODEL 2048
#define NHEADS 16
#define HDIM 128
#define NROWS (BSZ*SEQ)   // 4096

// Scratch (allocation-free rule: __device__ globals)
__device__ float g_q[BSZ*NHEADS*SEQ*HDIM];
__device__ float g_k[BSZ*NHEADS*SEQ*HDIM];
__device__ float g_v[BSZ*NHEADS*SEQ*HDIM];
__device__ float g_ctx[(size_t)BSZ*SEQ*DMODEL];

__device__ __forceinline__ uint32_t f32_to_tf32(float f) {
    uint32_t r;
    asm("cvt.rna.tf32.f32 %0, %1;" : "=r"(r) : "f"(f));
    return r;
}

__device__ __forceinline__ void mma_tf32_16x8x8(float c[4], const uint32_t a[4], const uint32_t b[2]) {
    asm volatile(
        "mma.sync.aligned.m16n8k8.row.col.f32.tf32.tf32.f32 "
        "{%0,%1,%2,%3}, {%4,%5,%6,%7}, {%8,%9}, {%0,%1,%2,%3};"
        : "+f"(c[0]), "+f"(c[1]), "+f"(c[2]), "+f"(c[3])
        : "r"(a[0]), "r"(a[1]), "r"(a[2]), "r"(a[3]), "r"(b[0]), "r"(b[1]));
}

__device__ __forceinline__ void mma_bf16_16x8x16(float c[4], const uint32_t a[4], uint32_t b0, uint32_t b1) {
    asm volatile(
        "mma.sync.aligned.m16n8k16.row.col.f32.bf16.bf16.f32 "
        "{%0,%1,%2,%3}, {%4,%5,%6,%7}, {%8,%9}, {%0,%1,%2,%3};"
        : "+f"(c[0]), "+f"(c[1]), "+f"(c[2]), "+f"(c[3])
        : "r"(a[0]), "r"(a[1]), "r"(a[2]), "r"(a[3]), "r"(b0), "r"(b1));
}

// pack two floats to bf16x2 (x -> low half, y -> high half)
__device__ __forceinline__ uint32_t pack_bf2(float x, float y) {
    __nv_bfloat162 h = __float22bfloat162_rn(make_float2(x, y));
    return *(uint32_t*)&h;
}
// reconstruct the two f32 values a bf16x2 word represents
__device__ __forceinline__ float bf2_lo_f32(uint32_t w) { return __uint_as_float(w << 16); }
__device__ __forceinline__ float bf2_hi_f32(uint32_t w) { return __uint_as_float(w & 0xffff0000u); }

// split pair (x,y) into hi word + lo (residual) word
__device__ __forceinline__ void split_bf2(float x, float y, uint32_t& hi, uint32_t& lo) {
    hi = pack_bf2(x, y);
    lo = pack_bf2(x - bf2_lo_f32(hi), y - bf2_hi_f32(hi));
}

// ---------------------------------------------------------------------------
// tf32 NT GEMM (unchanged from R3): C[M,N] = A[M,K] @ W[N,K]^T
// ---------------------------------------------------------------------------
template<int MODE>
__global__ void __launch_bounds__(256) gemm_tf32_kernel(
    const float* __restrict__ Ain,
    const float* __restrict__ W0,
    const float* __restrict__ W1,
    const float* __restrict__ W2,
    const float* __restrict__ bias,
    float* __restrict__ Cplain)
{
    __shared__ uint32_t As[32][136];
    __shared__ uint32_t Bs[32][136];

    const float* A;
    const float* W;
    float* dstQKV = nullptr;
    if (MODE == 0) {
        A = Ain;
        W = (blockIdx.z == 0) ? W0 : (blockIdx.z == 1 ? W1 : W2);
        dstQKV = (blockIdx.z == 0) ? g_q : (blockIdx.z == 1 ? g_k : g_v);
    } else {
        A = g_ctx;
        W = W0;
    }

    const int tid  = threadIdx.x;
    const int lane = tid & 31;
    const int wrp  = tid >> 5;
    const int wm   = (wrp >> 2) * 64;
    const int wn   = (wrp & 3) * 32;
    const int g    = lane >> 2;
    const int tg   = lane & 3;

    const int rowBase = blockIdx.y * 128;
    const int colBase = blockIdx.x * 128;

    float acc[4][4][4];
    #pragma unroll
    for (int i = 0; i < 4; i++)
        #pragma unroll
        for (int j = 0; j < 4; j++)
            #pragma unroll
            for (int c = 0; c < 4; c++) acc[i][j][c] = 0.f;

    for (int k0 = 0; k0 < DMODEL; k0 += 32) {
        #pragma unroll
        for (int p = 0; p < 4; p++) {
            int idx = tid + p * 256;
            int r  = idx >> 3;
            int kq = (idx & 7) << 2;
            float4 va = *(const float4*)(A + (size_t)(rowBase + r) * DMODEL + k0 + kq);
            As[kq+0][r] = f32_to_tf32(va.x);
            As[kq+1][r] = f32_to_tf32(va.y);
            As[kq+2][r] = f32_to_tf32(va.z);
            As[kq+3][r] = f32_to_tf32(va.w);
            float4 vb = *(const float4*)(W + (size_t)(colBase + r) * DMODEL + k0 + kq);
            Bs[kq+0][r] = f32_to_tf32(vb.x);
            Bs[kq+1][r] = f32_to_tf32(vb.y);
            Bs[kq+2][r] = f32_to_tf32(vb.z);
            Bs[kq+3][r] = f32_to_tf32(vb.w);
        }
        __syncthreads();

        #pragma unroll
        for (int kk = 0; kk < 4; kk++) {
            const int kb = kk * 8;
            uint32_t af[4][4], bf[4][2];
            #pragma unroll
            for (int i = 0; i < 4; i++) {
                int row = wm + i * 16 + g;
                af[i][0] = As[kb + tg    ][row];
                af[i][1] = As[kb + tg    ][row + 8];
                af[i][2] = As[kb + tg + 4][row];
                af[i][3] = As[kb + tg + 4][row + 8];
            }
            #pragma unroll
            for (int j = 0; j < 4; j++) {
                int col = wn + j * 8 + g;
                bf[j][0] = Bs[kb + tg    ][col];
                bf[j][1] = Bs[kb + tg + 4][col];
            }
            #pragma unroll
            for (int i = 0; i < 4; i++)
                #pragma unroll
                for (int j = 0; j < 4; j++)
                    mma_tf32_16x8x8(acc[i][j], af[i], bf[j]);
        }
        __syncthreads();
    }

    if (MODE == 0) {
        #pragma unroll
        for (int i = 0; i < 4; i++) {
            #pragma unroll
            for (int cc = 0; cc < 2; cc++) {
                int m = rowBase + wm + i * 16 + g + cc * 8;
                int b = m >> 11;
                int t = m & (SEQ - 1);
                size_t rowoff = ((size_t)(b * NHEADS) * SEQ + t) << 7;
                #pragma unroll
                for (int j = 0; j < 4; j++) {
                    int n0 = colBase + wn + j * 8 + tg * 2;
                    int h  = n0 >> 7;
                    int dh = n0 & (HDIM - 1);
                    float* dst = dstQKV + rowoff + (((size_t)h * SEQ) << 7) + dh;
                    dst[0] = acc[i][j][cc * 2 + 0];
                    dst[1] = acc[i][j][cc * 2 + 1];
                }
            }
        }
    } else {
        #pragma unroll
        for (int i = 0; i < 4; i++) {
            #pragma unroll
            for (int cc = 0; cc < 2; cc++) {
                int m = rowBase + wm + i * 16 + g + cc * 8;
                #pragma unroll
                for (int j = 0; j < 4; j++) {
                    int n0 = colBase + wn + j * 8 + tg * 2;
                    float2 v;
                    v.x = acc[i][j][cc * 2 + 0] + bias[n0];
                    v.y = acc[i][j][cc * 2 + 1] + bias[n0 + 1];
                    *(float2*)(Cplain + (size_t)m * DMODEL + n0) = v;
                }
            }
        }
    }
}

// ---------------------------------------------------------------------------
// RoPE in-place on g_q / g_k (unchanged).
// ---------------------------------------------------------------------------
__global__ void rope_kernel(const float* __restrict__ theta)
{
    int d = threadIdx.x;
    int t = blockIdx.x * 4 + threadIdx.y;
    int bh = blockIdx.y;
    float* buf = blockIdx.z ? g_k : g_q;
    float* row = buf + ((size_t)bh * SEQ + t) * HDIM;

    float ve = row[2*d];
    float vo = row[2*d+1];
    float f = (float)t * theta[d];
    float s, c;
    sincosf(f, &s, &c);
    __syncthreads();
    row[d]      = ve * c - vo * s;
    row[64 + d] = ve * s + vo * c;
}

// ---------------------------------------------------------------------------
// Tensor-core flash attention (bf16x3), causal.
// CTA: 128 q-rows x 64 k-cols per iteration, 256 threads = 8 warps,
// each warp owns 16 q-rows. SMEM words hold bf16x2 pairs (hi + residual lo).
//   Qhi/Qlo: [128][68]  pairs along d   (stride 68 -> conflict-free frags)
//   Khi/Klo: [64][68]   pairs along d
//   Vhi/Vlo: [128][36]  pairs along kpos (transposed at load; stride 36)
// ---------------------------------------------------------------------------
#define Q_STRIDE 68
#define V_STRIDE 36
#define SM_QHI 0
#define SM_QLO (SM_QHI + 128*Q_STRIDE)
#define SM_KHI (SM_QLO + 128*Q_STRIDE)
#define SM_KLO (SM_KHI + 64*Q_STRIDE)
#define SM_VHI (SM_KLO + 64*Q_STRIDE)
#define SM_VLO (SM_VHI + 128*V_STRIDE)
#define ATTN_SMEM_WORDS (SM_VLO + 128*V_STRIDE)

__global__ void __launch_bounds__(256, 1) attn_bf16_kernel()
{
    extern __shared__ uint32_t sm[];
    uint32_t* Qhi = sm + SM_QHI;
    uint32_t* Qlo = sm + SM_QLO;
    uint32_t* Khi = sm + SM_KHI;
    uint32_t* Klo = sm + SM_KLO;
    uint32_t* Vhi = sm + SM_VHI;
    uint32_t* Vlo = sm + SM_VLO;

    const int tid  = threadIdx.x;
    const int lane = tid & 31;
    const int wrp  = tid >> 5;      // 0..7
    const int g    = lane >> 2;     // 0..7
    const int tg   = lane & 3;      // 0..3
    const int wr   = wrp * 16;      // warp's q-row offset in tile

    const int qt = gridDim.x - 1 - blockIdx.x;   // big tiles first
    const int bh = blockIdx.y;
    const int qs = qt * 128;
    const size_t base = (size_t)bh * SEQ * HDIM;
    const float scale = 0.08838834764831845f;    // 1/sqrt(128)

    // ---- load Q tile + split: 128 rows x 32 float4 ----
    #pragma unroll
    for (int p = 0; p < 16; p++) {
        int idx = tid + p * 256;       // 0..4095
        int r   = idx >> 5;            // 0..127
        int c4  = idx & 31;            // float4 col
        float4 v = *(const float4*)(g_q + base + (size_t)(qs + r) * HDIM + c4 * 4);
        uint32_t h0, l0, h1, l1;
        split_bf2(v.x, v.y, h0, l0);
        split_bf2(v.z, v.w, h1, l1);
        Qhi[r * Q_STRIDE + c4*2    ] = h0;
        Qhi[r * Q_STRIDE + c4*2 + 1] = h1;
        Qlo[r * Q_STRIDE + c4*2    ] = l0;
        Qlo[r * Q_STRIDE + c4*2 + 1] = l1;
    }

    float o[16][4];
    #pragma unroll
    for (int j = 0; j < 16; j++)
        #pragma unroll
        for (int c = 0; c < 4; c++) o[j][c] = 0.f;
    float m0 = -INFINITY, m1 = -INFINITY, l0s = 0.f, l1s = 0.f;

    const int ktiles = 2 * qt + 2;
    for (int kt = 0; kt < ktiles; kt++) {
        const int ks = kt * 64;
        __syncthreads();   // smem safe to overwrite (and Q visible on first iter)

        // ---- load K tile + split: 64 rows x 32 float4 ----
        #pragma unroll
        for (int p = 0; p < 8; p++) {
            int idx = tid + p * 256;
            int r   = idx >> 5;        // 0..63
            int c4  = idx & 31;
            float4 v = *(const float4*)(g_k + base + (size_t)(ks + r) * HDIM + c4 * 4);
            uint32_t h0, l0, h1, l1;
            split_bf2(v.x, v.y, h0, l0);
            split_bf2(v.z, v.w, h1, l1);
            Khi[r * Q_STRIDE + c4*2    ] = h0;
            Khi[r * Q_STRIDE + c4*2 + 1] = h1;
            Klo[r * Q_STRIDE + c4*2    ] = l0;
            Klo[r * Q_STRIDE + c4*2 + 1] = l1;
        }
        // ---- load V tile transposed + split: pairs along kpos ----
        #pragma unroll
        for (int p = 0; p < 4; p++) {
            int u  = tid + p * 256;    // 0..1023
            int m2 = u & 31;           // kpos pair 0..31
            int d0 = (u >> 5) * 4;     // 0,4,...,124
            float4 va = *(const float4*)(g_v + base + (size_t)(ks + 2*m2    ) * HDIM + d0);
            float4 vb = *(const float4*)(g_v + base + (size_t)(ks + 2*m2 + 1) * HDIM + d0);
            const float* pa = &va.x;
            const float* pb = &vb.x;
            #pragma unroll
            for (int i = 0; i < 4; i++) {
                uint32_t h, l;
                split_bf2(pa[i], pb[i], h, l);
                Vhi[(d0 + i) * V_STRIDE + m2] = h;
                Vlo[(d0 + i) * V_STRIDE + m2] = l;
            }
        }
        __syncthreads();

        // ---- S = Q K^T  (8 k-steps of 16 over d) ----
        float sc[8][4];
        #pragma unroll
        for (int j = 0; j < 8; j++)
            #pragma unroll
            for (int c = 0; c < 4; c++) sc[j][c] = 0.f;

        const int ra0 = (wr + g) * Q_STRIDE;
        const int ra1 = (wr + g + 8) * Q_STRIDE;
        #pragma unroll
        for (int kk = 0; kk < 8; kk++) {
            const int kw = kk * 8;
            uint32_t ah[4], al[4];
            ah[0] = Qhi[ra0 + kw + tg];     al[0] = Qlo[ra0 + kw + tg];
            ah[1] = Qhi[ra1 + kw + tg];     al[1] = Qlo[ra1 + kw + tg];
            ah[2] = Qhi[ra0 + kw + tg + 4]; al[2] = Qlo[ra0 + kw + tg + 4];
            ah[3] = Qhi[ra1 + kw + tg + 4]; al[3] = Qlo[ra1 + kw + tg + 4];
            #pragma unroll
            for (int j = 0; j < 8; j++) {
                const int rb = (j * 8 + g) * Q_STRIDE + kw;
                uint32_t bh0 = Khi[rb + tg], bh1 = Khi[rb + tg + 4];
                uint32_t bl0 = Klo[rb + tg], bl1 = Klo[rb + tg + 4];
                mma_bf16_16x8x16(sc[j], ah, bh0, bh1);
                mma_bf16_16x8x16(sc[j], ah, bl0, bl1);
                mma_bf16_16x8x16(sc[j], al, bh0, bh1);
            }
        }

        // ---- scale + causal mask ----
        const int r0 = qs + wr + g;
        const int r1 = r0 + 8;
        const bool part = (ks + 63 > qs + wr);
        #pragma unroll
        for (int j = 0; j < 8; j++) {
            int cb = ks + j * 8 + 2 * tg;
            sc[j][0] = (part && cb     > r0) ? -1e30f : sc[j][0] * scale;
            sc[j][1] = (part && cb + 1 > r0) ? -1e30f : sc[j][1] * scale;
            sc[j][2] = (part && cb     > r1) ? -1e30f : sc[j][2] * scale;
            sc[j][3] = (part && cb + 1 > r1) ? -1e30f : sc[j][3] * scale;
        }

        // ---- online softmax (rows fully warp-owned; reduce over tg quad) ----
        float mx0 = -INFINITY, mx1 = -INFINITY;
        #pragma unroll
        for (int j = 0; j < 8; j++) {
            mx0 = fmaxf(mx0, fmaxf(sc[j][0], sc[j][1]));
            mx1 = fmaxf(mx1, fmaxf(sc[j][2], sc[j][3]));
        }
        mx0 = fmaxf(mx0, __shfl_xor_sync(0xffffffff, mx0, 1));
        mx0 = fmaxf(mx0, __shfl_xor_sync(0xffffffff, mx0, 2));
        mx1 = fmaxf(mx1, __shfl_xor_sync(0xffffffff, mx1, 1));
        mx1 = fmaxf(mx1, __shfl_xor_sync(0xffffffff, mx1, 2));

        float nm0 = fmaxf(m0, mx0);
        float nm1 = fmaxf(m1, mx1);
        float fac0 = __expf(m0 - nm0);
        float fac1 = __expf(m1 - nm1);
        m0 = nm0; m1 = nm1;

        float sum0 = 0.f, sum1 = 0.f;
        #pragma unroll
        for (int j = 0; j < 8; j++) {
            sc[j][0] = __expf(sc[j][0] - m0); sum0 += sc[j][0];
            sc[j][1] = __expf(sc[j][1] - m0); sum0 += sc[j][1];
            sc[j][2] = __expf(sc[j][2] - m1); sum1 += sc[j][2];
            sc[j][3] = __expf(sc[j][3] - m1); sum1 += sc[j][3];
        }
        sum0 += __shfl_xor_sync(0xffffffff, sum0, 1);
        sum0 += __shfl_xor_sync(0xffffffff, sum0, 2);
        sum1 += __shfl_xor_sync(0xffffffff, sum1, 1);
        sum1 += __shfl_xor_sync(0xffffffff, sum1, 2);
        l0s = l0s * fac0 + sum0;
        l1s = l1s * fac1 + sum1;

        #pragma unroll
        for (int j = 0; j < 16; j++) {
            o[j][0] *= fac0; o[j][1] *= fac0;
            o[j][2] *= fac1; o[j][3] *= fac1;
        }

        // ---- O += P V  (P stays in registers: C-frag -> A-frag identity) ----
        #pragma unroll
        for (int k2 = 0; k2 < 4; k2++) {
            uint32_t ah[4], al[4];
            split_bf2(sc[2*k2  ][0], sc[2*k2  ][1], ah[0], al[0]);
            split_bf2(sc[2*k2  ][2], sc[2*k2  ][3], ah[1], al[1]);
            split_bf2(sc[2*k2+1][0], sc[2*k2+1][1], ah[2], al[2]);
            split_bf2(sc[2*k2+1][2], sc[2*k2+1][3], ah[3], al[3]);
            #pragma unroll
            for (int jd = 0; jd < 16; jd++) {
                const int rb = (jd * 8 + g) * V_STRIDE + k2 * 8;
                uint32_t bh0 = Vhi[rb + tg], bh1 = Vhi[rb + tg + 4];
                uint32_t bl0 = Vlo[rb + tg], bl1 = Vlo[rb + tg + 4];
                mma_bf16_16x8x16(o[jd], ah, bh0, bh1);
                mma_bf16_16x8x16(o[jd], ah, bl0, bl1);
                mma_bf16_16x8x16(o[jd], al, bh0, bh1);
            }
        }
    }

    // ---- epilogue: write ctx [b, t, h*128 + d] ----
    const float inv0 = 1.f / l0s;
    const float inv1 = 1.f / l1s;
    const int b = bh >> 4;
    const int h = bh & 15;
    const int r0 = qs + wr + g;
    float* dst0 = g_ctx + ((size_t)(b * SEQ + r0    ) * DMODEL) + h * HDIM;
    float* dst1 = g_ctx + ((size_t)(b * SEQ + r0 + 8) * DMODEL) + h * HDIM;
    #pragma unroll
    for (int jd = 0; jd < 16; jd++) {
        int d0 = jd * 8 + 2 * tg;
        *(float2*)(dst0 + d0) = make_float2(o[jd][0] * inv0, o[jd][1] * inv0);
        *(float2*)(dst1 + d0) = make_float2(o[jd][2] * inv1, o[jd][3] * inv1);
    }
}

// ---------------------------------------------------------------------------
extern "C" void kernel_launch(void* const* d_in, const int* in_sizes, int n_in,
                              void* d_out, int out_size)
{
    const float* x     = (const float*)d_in[0];
    const float* Wq    = (const float*)d_in[1];
    const float* Wk    = (const float*)d_in[2];
    const float* Wv    = (const float*)d_in[3];
    const float* Wo    = (const float*)d_in[4];
    const float* bo    = (const float*)d_in[5];
    const float* theta = (const float*)d_in[6];
    float* out = (float*)d_out;

    // 1. QKV projections (tf32 tensor cores), scatter to [b,h,t,dh]
    gemm_tf32_kernel<0><<<dim3(DMODEL/128, NROWS/128, 3), 256>>>(x, Wq, Wk, Wv, nullptr, nullptr);

    // 2. RoPE on q and k
    rope_kernel<<<dim3(SEQ/4, BSZ*NHEADS, 2), dim3(64, 4)>>>(theta);

    // 3. Causal flash attention (bf16x3 tensor cores)
    const int smem_bytes = ATTN_SMEM_WORDS * (int)sizeof(uint32_t);
    cudaFuncSetAttribute(attn_bf16_kernel, cudaFuncAttributeMaxDynamicSharedMemorySize, smem_bytes);
    attn_bf16_kernel<<<dim3(SEQ/128, BSZ*NHEADS), 256, smem_bytes>>>();

    // 4. Output projection + bias (tf32 tensor cores)
    gemm_tf32_kernel<1><<<dim3(DMODEL/128, NROWS/128, 1), 256>>>(nullptr, Wo, nullptr, nullptr, bo, out);
}

// round 5
// speedup vs baseline: 3.9780x; 1.5622x over previous
#include <cuda_runtime.h>
#include <cuda_bf16.h>
#include <math.h>
#include <stdint.h>

#define BSZ 2
#define SEQ 2048
#define DMODEL 2048
#define NHEADS 16
#define HDIM 128
#define NROWS (BSZ*SEQ)   // 4096
#define WSZ (DMODEL*DMODEL)

// Scratch (allocation-free rule: __device__ globals)
__device__ float    g_q[BSZ*NHEADS*SEQ*HDIM];
__device__ float    g_k[BSZ*NHEADS*SEQ*HDIM];
__device__ float    g_v[BSZ*NHEADS*SEQ*HDIM];
__device__ uint32_t g_ctx[(size_t)BSZ*SEQ*DMODEL];     // tf32 bits of attention output
__device__ uint32_t g_xt[(size_t)NROWS*DMODEL];        // tf32 bits of x
__device__ uint32_t g_wt[(size_t)4*WSZ];               // tf32 bits of Wq,Wk,Wv,Wo

__device__ __forceinline__ uint32_t f32_to_tf32(float f) {
    uint32_t r;
    asm("cvt.rna.tf32.f32 %0, %1;" : "=r"(r) : "f"(f));
    return r;
}

__device__ __forceinline__ void mma_tf32_16x8x8(float c[4], const uint32_t a[4], uint32_t b0, uint32_t b1) {
    asm volatile(
        "mma.sync.aligned.m16n8k8.row.col.f32.tf32.tf32.f32 "
        "{%0,%1,%2,%3}, {%4,%5,%6,%7}, {%8,%9}, {%0,%1,%2,%3};"
        : "+f"(c[0]), "+f"(c[1]), "+f"(c[2]), "+f"(c[3])
        : "r"(a[0]), "r"(a[1]), "r"(a[2]), "r"(a[3]), "r"(b0), "r"(b1));
}

__device__ __forceinline__ void mma_bf16_16x8x16(float c[4], const uint32_t a[4], uint32_t b0, uint32_t b1) {
    asm volatile(
        "mma.sync.aligned.m16n8k16.row.col.f32.bf16.bf16.f32 "
        "{%0,%1,%2,%3}, {%4,%5,%6,%7}, {%8,%9}, {%0,%1,%2,%3};"
        : "+f"(c[0]), "+f"(c[1]), "+f"(c[2]), "+f"(c[3])
        : "r"(a[0]), "r"(a[1]), "r"(a[2]), "r"(a[3]), "r"(b0), "r"(b1));
}

__device__ __forceinline__ uint32_t pack_bf2(float x, float y) {
    __nv_bfloat162 h = __float22bfloat162_rn(make_float2(x, y));
    return *(uint32_t*)&h;
}
__device__ __forceinline__ float bf2_lo_f32(uint32_t w) { return __uint_as_float(w << 16); }
__device__ __forceinline__ float bf2_hi_f32(uint32_t w) { return __uint_as_float(w & 0xffff0000u); }
__device__ __forceinline__ void split_bf2(float x, float y, uint32_t& hi, uint32_t& lo) {
    hi = pack_bf2(x, y);
    lo = pack_bf2(x - bf2_lo_f32(hi), y - bf2_hi_f32(hi));
}

__device__ __forceinline__ void cp16(uint32_t* dst, const uint32_t* src) {
    uint32_t s = (uint32_t)__cvta_generic_to_shared(dst);
    asm volatile("cp.async.cg.shared.global [%0], [%1], 16;" :: "r"(s), "l"(src));
}
__device__ __forceinline__ void cp_commit() { asm volatile("cp.async.commit_group;"); }
template<int N> __device__ __forceinline__ void cp_wait() { asm volatile("cp.async.wait_group %0;" :: "n"(N)); }

// ---------------------------------------------------------------------------
// Elementwise f32 -> tf32-bits convert (vectorized)
// ---------------------------------------------------------------------------
__global__ void cvt_tf32_kernel(const float4* __restrict__ src, uint4* __restrict__ dst, int n4)
{
    int i = blockIdx.x * 256 + threadIdx.x;
    if (i < n4) {
        float4 v = src[i];
        dst[i] = make_uint4(f32_to_tf32(v.x), f32_to_tf32(v.y), f32_to_tf32(v.z), f32_to_tf32(v.w));
    }
}

// ---------------------------------------------------------------------------
// tf32 NT GEMM, cp.async 3-stage pipeline.
// C[M,N] = A[M,K] @ W[N,K]^T, operands are pre-converted tf32 bits.
// Block 128x256, BK=32, 256 threads = 8 warps (2x4), warp tile 64x64.
// MODE 0: z selects W (g_wt + z*WSZ), epilogue scatters to g_q/g_k/g_v [b,h,t,dh]
// MODE 1: A = g_ctx bits, W = Wo bits, adds bias, writes f32 row-major to Cplain
// ---------------------------------------------------------------------------
#define ASTRIDE 36
#define STAGE_A_WORDS (128*ASTRIDE)                    // 4608
#define STAGE_B_WORDS (256*ASTRIDE)                    // 9216
#define STAGE_WORDS   (STAGE_A_WORDS + STAGE_B_WORDS)  // 13824
#define NSTAGES 3
#define GEMM_SMEM_BYTES (NSTAGES * STAGE_WORDS * 4)    // 165888

template<int MODE>
__global__ void __launch_bounds__(256, 1) gemm_tc_kernel(
    const uint32_t* __restrict__ Abits,
    const uint32_t* __restrict__ Wbase,
    const float* __restrict__ bias,
    float* __restrict__ Cplain)
{
    extern __shared__ uint32_t sh[];

    const int tid  = threadIdx.x;
    const int lane = tid & 31;
    const int wrp  = tid >> 5;
    const int g    = lane >> 2;
    const int tg   = lane & 3;
    const int wm   = (wrp >> 2) * 64;    // warp row offset (2 row-warps)
    const int wn   = (wrp & 3) * 64;     // warp col offset (4 col-warps)

    const int rowBase = blockIdx.y * 128;
    const int colBase = blockIdx.x * 256;

    const uint32_t* W = (MODE == 0) ? (Wbase + (size_t)blockIdx.z * WSZ) : Wbase;
    float* dstQKV = nullptr;
    if (MODE == 0)
        dstQKV = (blockIdx.z == 0) ? g_q : (blockIdx.z == 1 ? g_k : g_v);

    const uint32_t* Aip = Abits + (size_t)rowBase * DMODEL;
    const uint32_t* Wip = W + (size_t)colBase * DMODEL;

    auto issue = [&](int kt, int s) {
        uint32_t* as = sh + s * STAGE_WORDS;
        uint32_t* bs = as + STAGE_A_WORDS;
        const uint32_t* ag = Aip + kt * 32;
        const uint32_t* bg = Wip + kt * 32;
        #pragma unroll
        for (int p = 0; p < 4; p++) {
            int c = tid + p * 256;       // 0..1023
            int r = c >> 3;
            int c4 = (c & 7) << 2;
            cp16(as + r * ASTRIDE + c4, ag + (size_t)r * DMODEL + c4);
        }
        #pragma unroll
        for (int p = 0; p < 8; p++) {
            int c = tid + p * 256;       // 0..2047
            int r = c >> 3;
            int c4 = (c & 7) << 2;
            cp16(bs + r * ASTRIDE + c4, bg + (size_t)r * DMODEL + c4);
        }
    };

    float acc[4][8][4];
    #pragma unroll
    for (int i = 0; i < 4; i++)
        #pragma unroll
        for (int j = 0; j < 8; j++)
            #pragma unroll
            for (int c = 0; c < 4; c++) acc[i][j][c] = 0.f;

    issue(0, 0); cp_commit();
    issue(1, 1); cp_commit();

    const int NKT = DMODEL / 32;   // 64
    for (int kt = 0; kt < NKT; kt++) {
        cp_wait<1>();
        __syncthreads();
        if (kt + 2 < NKT) issue(kt + 2, (kt + 2) % NSTAGES);
        cp_commit();

        const uint32_t* as = sh + (kt % NSTAGES) * STAGE_WORDS;
        const uint32_t* bs = as + STAGE_A_WORDS;

        #pragma unroll
        for (int kk = 0; kk < 4; kk++) {
            const int kb = kk * 8;
            uint32_t af[4][4];
            #pragma unroll
            for (int i = 0; i < 4; i++) {
                const int m0 = (wm + i * 16 + g) * ASTRIDE + kb;
                af[i][0] = as[m0 + tg];
                af[i][1] = as[m0 + 8 * ASTRIDE + tg];
                af[i][2] = as[m0 + tg + 4];
                af[i][3] = as[m0 + 8 * ASTRIDE + tg + 4];
            }
            #pragma unroll
            for (int j = 0; j < 8; j++) {
                const int n0 = (wn + j * 8 + g) * ASTRIDE + kb;
                uint32_t b0 = bs[n0 + tg];
                uint32_t b1 = bs[n0 + tg + 4];
                #pragma unroll
                for (int i = 0; i < 4; i++)
                    mma_tf32_16x8x8(acc[i][j], af[i], b0, b1);
            }
        }
    }

    if (MODE == 0) {
        #pragma unroll
        for (int i = 0; i < 4; i++) {
            #pragma unroll
            for (int cc = 0; cc < 2; cc++) {
                int m = rowBase + wm + i * 16 + g + cc * 8;
                int b = m >> 11;
                int t = m & (SEQ - 1);
                size_t rowoff = ((size_t)(b * NHEADS) * SEQ + t) << 7;
                #pragma unroll
                for (int j = 0; j < 8; j++) {
                    int n0 = colBase + wn + j * 8 + tg * 2;
                    int h  = n0 >> 7;
                    int dh = n0 & (HDIM - 1);
                    float* dst = dstQKV + rowoff + (((size_t)h * SEQ) << 7) + dh;
                    dst[0] = acc[i][j][cc * 2 + 0];
                    dst[1] = acc[i][j][cc * 2 + 1];
                }
            }
        }
    } else {
        #pragma unroll
        for (int i = 0; i < 4; i++) {
            #pragma unroll
            for (int cc = 0; cc < 2; cc++) {
                int m = rowBase + wm + i * 16 + g + cc * 8;
                #pragma unroll
                for (int j = 0; j < 8; j++) {
                    int n0 = colBase + wn + j * 8 + tg * 2;
                    float2 v;
                    v.x = acc[i][j][cc * 2 + 0] + bias[n0];
                    v.y = acc[i][j][cc * 2 + 1] + bias[n0 + 1];
                    *(float2*)(Cplain + (size_t)m * DMODEL + n0) = v;
                }
            }
        }
    }
}

// ---------------------------------------------------------------------------
// RoPE in-place on g_q / g_k (unchanged).
// ---------------------------------------------------------------------------
__global__ void rope_kernel(const float* __restrict__ theta)
{
    int d = threadIdx.x;
    int t = blockIdx.x * 4 + threadIdx.y;
    int bh = blockIdx.y;
    float* buf = blockIdx.z ? g_k : g_q;
    float* row = buf + ((size_t)bh * SEQ + t) * HDIM;

    float ve = row[2*d];
    float vo = row[2*d+1];
    float f = (float)t * theta[d];
    float s, c;
    sincosf(f, &s, &c);
    __syncthreads();
    row[d]      = ve * c - vo * s;
    row[64 + d] = ve * s + vo * c;
}

// ---------------------------------------------------------------------------
// Tensor-core flash attention (bf16x3), causal. Epilogue now emits tf32 bits.
// ---------------------------------------------------------------------------
#define Q_STRIDE 68
#define V_STRIDE 36
#define SM_QHI 0
#define SM_QLO (SM_QHI + 128*Q_STRIDE)
#define SM_KHI (SM_QLO + 128*Q_STRIDE)
#define SM_KLO (SM_KHI + 64*Q_STRIDE)
#define SM_VHI (SM_KLO + 64*Q_STRIDE)
#define SM_VLO (SM_VHI + 128*V_STRIDE)
#define ATTN_SMEM_WORDS (SM_VLO + 128*V_STRIDE)

__global__ void __launch_bounds__(256, 1) attn_bf16_kernel()
{
    extern __shared__ uint32_t sm[];
    uint32_t* Qhi = sm + SM_QHI;
    uint32_t* Qlo = sm + SM_QLO;
    uint32_t* Khi = sm + SM_KHI;
    uint32_t* Klo = sm + SM_KLO;
    uint32_t* Vhi = sm + SM_VHI;
    uint32_t* Vlo = sm + SM_VLO;

    const int tid  = threadIdx.x;
    const int lane = tid & 31;
    const int wrp  = tid >> 5;
    const int g    = lane >> 2;
    const int tg   = lane & 3;
    const int wr   = wrp * 16;

    const int qt = gridDim.x - 1 - blockIdx.x;   // big tiles first
    const int bh = blockIdx.y;
    const int qs = qt * 128;
    const size_t base = (size_t)bh * SEQ * HDIM;
    const float scale = 0.08838834764831845f;

    #pragma unroll
    for (int p = 0; p < 16; p++) {
        int idx = tid + p * 256;
        int r   = idx >> 5;
        int c4  = idx & 31;
        float4 v = *(const float4*)(g_q + base + (size_t)(qs + r) * HDIM + c4 * 4);
        uint32_t h0, l0, h1, l1;
        split_bf2(v.x, v.y, h0, l0);
        split_bf2(v.z, v.w, h1, l1);
        Qhi[r * Q_STRIDE + c4*2    ] = h0;
        Qhi[r * Q_STRIDE + c4*2 + 1] = h1;
        Qlo[r * Q_STRIDE + c4*2    ] = l0;
        Qlo[r * Q_STRIDE + c4*2 + 1] = l1;
    }

    float o[16][4];
    #pragma unroll
    for (int j = 0; j < 16; j++)
        #pragma unroll
        for (int c = 0; c < 4; c++) o[j][c] = 0.f;
    float m0 = -INFINITY, m1 = -INFINITY, l0s = 0.f, l1s = 0.f;

    const int ktiles = 2 * qt + 2;
    for (int kt = 0; kt < ktiles; kt++) {
        const int ks = kt * 64;
        __syncthreads();

        #pragma unroll
        for (int p = 0; p < 8; p++) {
            int idx = tid + p * 256;
            int r   = idx >> 5;
            int c4  = idx & 31;
            float4 v = *(const float4*)(g_k + base + (size_t)(ks + r) * HDIM + c4 * 4);
            uint32_t h0, l0, h1, l1;
            split_bf2(v.x, v.y, h0, l0);
            split_bf2(v.z, v.w, h1, l1);
            Khi[r * Q_STRIDE + c4*2    ] = h0;
            Khi[r * Q_STRIDE + c4*2 + 1] = h1;
            Klo[r * Q_STRIDE + c4*2    ] = l0;
            Klo[r * Q_STRIDE + c4*2 + 1] = l1;
        }
        #pragma unroll
        for (int p = 0; p < 4; p++) {
            int u  = tid + p * 256;
            int m2 = u & 31;
            int d0 = (u >> 5) * 4;
            float4 va = *(const float4*)(g_v + base + (size_t)(ks + 2*m2    ) * HDIM + d0);
            float4 vb = *(const float4*)(g_v + base + (size_t)(ks + 2*m2 + 1) * HDIM + d0);
            const float* pa = &va.x;
            const float* pb = &vb.x;
            #pragma unroll
            for (int i = 0; i < 4; i++) {
                uint32_t h, l;
                split_bf2(pa[i], pb[i], h, l);
                Vhi[(d0 + i) * V_STRIDE + m2] = h;
                Vlo[(d0 + i) * V_STRIDE + m2] = l;
            }
        }
        __syncthreads();

        float sc[8][4];
        #pragma unroll
        for (int j = 0; j < 8; j++)
            #pragma unroll
            for (int c = 0; c < 4; c++) sc[j][c] = 0.f;

        const int ra0 = (wr + g) * Q_STRIDE;
        const int ra1 = (wr + g + 8) * Q_STRIDE;
        #pragma unroll
        for (int kk = 0; kk < 8; kk++) {
            const int kw = kk * 8;
            uint32_t ah[4], al[4];
            ah[0] = Qhi[ra0 + kw + tg];     al[0] = Qlo[ra0 + kw + tg];
            ah[1] = Qhi[ra1 + kw + tg];     al[1] = Qlo[ra1 + kw + tg];
            ah[2] = Qhi[ra0 + kw + tg + 4]; al[2] = Qlo[ra0 + kw + tg + 4];
            ah[3] = Qhi[ra1 + kw + tg + 4]; al[3] = Qlo[ra1 + kw + tg + 4];
            #pragma unroll
            for (int j = 0; j < 8; j++) {
                const int rb = (j * 8 + g) * Q_STRIDE + kw;
                uint32_t bh0 = Khi[rb + tg], bh1 = Khi[rb + tg + 4];
                uint32_t bl0 = Klo[rb + tg], bl1 = Klo[rb + tg + 4];
                mma_bf16_16x8x16(sc[j], ah, bh0, bh1);
                mma_bf16_16x8x16(sc[j], ah, bl0, bl1);
                mma_bf16_16x8x16(sc[j], al, bh0, bh1);
            }
        }

        const int r0 = qs + wr + g;
        const int r1 = r0 + 8;
        const bool part = (ks + 63 > qs + wr);
        #pragma unroll
        for (int j = 0; j < 8; j++) {
            int cb = ks + j * 8 + 2 * tg;
            sc[j][0] = (part && cb     > r0) ? -1e30f : sc[j][0] * scale;
            sc[j][1] = (part && cb + 1 > r0) ? -1e30f : sc[j][1] * scale;
            sc[j][2] = (part && cb     > r1) ? -1e30f : sc[j][2] * scale;
            sc[j][3] = (part && cb + 1 > r1) ? -1e30f : sc[j][3] * scale;
        }

        float mx0 = -INFINITY, mx1 = -INFINITY;
        #pragma unroll
        for (int j = 0; j < 8; j++) {
            mx0 = fmaxf(mx0, fmaxf(sc[j][0], sc[j][1]));
            mx1 = fmaxf(mx1, fmaxf(sc[j][2], sc[j][3]));
        }
        mx0 = fmaxf(mx0, __shfl_xor_sync(0xffffffff, mx0, 1));
        mx0 = fmaxf(mx0, __shfl_xor_sync(0xffffffff, mx0, 2));
        mx1 = fmaxf(mx1, __shfl_xor_sync(0xffffffff, mx1, 1));
        mx1 = fmaxf(mx1, __shfl_xor_sync(0xffffffff, mx1, 2));

        float nm0 = fmaxf(m0, mx0);
        float nm1 = fmaxf(m1, mx1);
        float fac0 = __expf(m0 - nm0);
        float fac1 = __expf(m1 - nm1);
        m0 = nm0; m1 = nm1;

        float sum0 = 0.f, sum1 = 0.f;
        #pragma unroll
        for (int j = 0; j < 8; j++) {
            sc[j][0] = __expf(sc[j][0] - m0); sum0 += sc[j][0];
            sc[j][1] = __expf(sc[j][1] - m0); sum0 += sc[j][1];
            sc[j][2] = __expf(sc[j][2] - m1); sum1 += sc[j][2];
            sc[j][3] = __expf(sc[j][3] - m1); sum1 += sc[j][3];
        }
        sum0 += __shfl_xor_sync(0xffffffff, sum0, 1);
        sum0 += __shfl_xor_sync(0xffffffff, sum0, 2);
        sum1 += __shfl_xor_sync(0xffffffff, sum1, 1);
        sum1 += __shfl_xor_sync(0xffffffff, sum1, 2);
        l0s = l0s * fac0 + sum0;
        l1s = l1s * fac1 + sum1;

        #pragma unroll
        for (int j = 0; j < 16; j++) {
            o[j][0] *= fac0; o[j][1] *= fac0;
            o[j][2] *= fac1; o[j][3] *= fac1;
        }

        #pragma unroll
        for (int k2 = 0; k2 < 4; k2++) {
            uint32_t ah[4], al[4];
            split_bf2(sc[2*k2  ][0], sc[2*k2  ][1], ah[0], al[0]);
            split_bf2(sc[2*k2  ][2], sc[2*k2  ][3], ah[1], al[1]);
            split_bf2(sc[2*k2+1][0], sc[2*k2+1][1], ah[2], al[2]);
            split_bf2(sc[2*k2+1][2], sc[2*k2+1][3], ah[3], al[3]);
            #pragma unroll
            for (int jd = 0; jd < 16; jd++) {
                const int rb = (jd * 8 + g) * V_STRIDE + k2 * 8;
                uint32_t bh0 = Vhi[rb + tg], bh1 = Vhi[rb + tg + 4];
                uint32_t bl0 = Vlo[rb + tg], bl1 = Vlo[rb + tg + 4];
                mma_bf16_16x8x16(o[jd], ah, bh0, bh1);
                mma_bf16_16x8x16(o[jd], ah, bl0, bl1);
                mma_bf16_16x8x16(o[jd], al, bh0, bh1);
            }
        }
    }

    // ---- epilogue: write ctx as tf32 bits, [b, t, h*128 + d] ----
    const float inv0 = 1.f / l0s;
    const float inv1 = 1.f / l1s;
    const int b = bh >> 4;
    const int h = bh & 15;
    const int r0 = qs + wr + g;
    uint32_t* dst0 = g_ctx + ((size_t)(b * SEQ + r0    ) * DMODEL) + h * HDIM;
    uint32_t* dst1 = g_ctx + ((size_t)(b * SEQ + r0 + 8) * DMODEL) + h * HDIM;
    #pragma unroll
    for (int jd = 0; jd < 16; jd++) {
        int d0 = jd * 8 + 2 * tg;
        *(uint2*)(dst0 + d0) = make_uint2(f32_to_tf32(o[jd][0] * inv0), f32_to_tf32(o[jd][1] * inv0));
        *(uint2*)(dst1 + d0) = make_uint2(f32_to_tf32(o[jd][2] * inv1), f32_to_tf32(o[jd][3] * inv1));
    }
}

// ---------------------------------------------------------------------------
extern "C" void kernel_launch(void* const* d_in, const int* in_sizes, int n_in,
                              void* d_out, int out_size)
{
    const float* x     = (const float*)d_in[0];
    const float* Wq    = (const float*)d_in[1];
    const float* Wk    = (const float*)d_in[2];
    const float* Wv    = (const float*)d_in[3];
    const float* Wo    = (const float*)d_in[4];
    const float* bo    = (const float*)d_in[5];
    const float* theta = (const float*)d_in[6];
    float* out = (float*)d_out;

    uint32_t* xt;  cudaGetSymbolAddress((void**)&xt, g_xt);
    uint32_t* wt;  cudaGetSymbolAddress((void**)&wt, g_wt);
    uint32_t* ctx; cudaGetSymbolAddress((void**)&ctx, g_ctx);

    // 0. Pre-convert operands to tf32 bits
    cvt_tf32_kernel<<<(NROWS*DMODEL/4 + 255)/256, 256>>>((const float4*)x,  (uint4*)xt, NROWS*DMODEL/4);
    cvt_tf32_kernel<<<(WSZ/4 + 255)/256, 256>>>((const float4*)Wq, (uint4*)(wt + 0*(size_t)WSZ), WSZ/4);
    cvt_tf32_kernel<<<(WSZ/4 + 255)/256, 256>>>((const float4*)Wk, (uint4*)(wt + 1*(size_t)WSZ), WSZ/4);
    cvt_tf32_kernel<<<(WSZ/4 + 255)/256, 256>>>((const float4*)Wv, (uint4*)(wt + 2*(size_t)WSZ), WSZ/4);
    cvt_tf32_kernel<<<(WSZ/4 + 255)/256, 256>>>((const float4*)Wo, (uint4*)(wt + 3*(size_t)WSZ), WSZ/4);

    // 1. QKV projections (tf32 mma + cp.async pipeline), scatter to [b,h,t,dh]
    cudaFuncSetAttribute(gemm_tc_kernel<0>, cudaFuncAttributeMaxDynamicSharedMemorySize, GEMM_SMEM_BYTES);
    gemm_tc_kernel<0><<<dim3(DMODEL/256, NROWS/128, 3), 256, GEMM_SMEM_BYTES>>>(xt, wt, nullptr, nullptr);

    // 2. RoPE on q and k
    rope_kernel<<<dim3(SEQ/4, BSZ*NHEADS, 2), dim3(64, 4)>>>(theta);

    // 3. Causal flash attention (bf16x3 tensor cores), emits tf32-bit ctx
    const int attn_smem = ATTN_SMEM_WORDS * (int)sizeof(uint32_t);
    cudaFuncSetAttribute(attn_bf16_kernel, cudaFuncAttributeMaxDynamicSharedMemorySize, attn_smem);
    attn_bf16_kernel<<<dim3(SEQ/128, BSZ*NHEADS), 256, attn_smem>>>();

    // 4. Output projection + bias
    cudaFuncSetAttribute(gemm_tc_kernel<1>, cudaFuncAttributeMaxDynamicSharedMemorySize, GEMM_SMEM_BYTES);
    gemm_tc_kernel<1><<<dim3(DMODEL/256, NROWS/128, 1), 256, GEMM_SMEM_BYTES>>>(ctx, wt + 3*(size_t)WSZ, bo, out);
}

// round 7
// speedup vs baseline: 4.4284x; 1.1132x over previous
#include <cuda_runtime.h>
#include <cuda_bf16.h>
#include <math.h>
#include <stdint.h>

#define BSZ 2
#define SEQ 2048
#define DMODEL 2048
#define NHEADS 16
#define HDIM 128
#define NROWS (BSZ*SEQ)     // 4096
#define WSZ (DMODEL*DMODEL)
#define KBLKS (DMODEL/8)    // 256 k8-blocks per row
#define NB2T (DMODEL/16)    // 128 n16-blocks

// Scratch (allocation-free rule: __device__ globals)
__device__ float    g_q[BSZ*NHEADS*SEQ*HDIM];
__device__ float    g_k[BSZ*NHEADS*SEQ*HDIM];
__device__ float    g_v[BSZ*NHEADS*SEQ*HDIM];
__device__ uint32_t g_xp[(size_t)NROWS*DMODEL];   // x, tf32 bits, A-fragment-permuted
__device__ uint32_t g_wp[(size_t)4*WSZ];          // Wq,Wk,Wv,Wo tf32 bits, B-fragment-permuted
__device__ uint32_t g_cp[(size_t)NROWS*DMODEL];   // ctx, tf32 bits, A-fragment-permuted

// ---------------------------------------------------------------------------
// helpers
// ---------------------------------------------------------------------------
__device__ __forceinline__ uint32_t f32_to_tf32(float f) {
    uint32_t r;
    asm("cvt.rna.tf32.f32 %0, %1;" : "=r"(r) : "f"(f));
    return r;
}

__device__ __forceinline__ void mma_tf32_16x8x8(float c[4], const uint32_t a[4], uint32_t b0, uint32_t b1) {
    asm volatile(
        "mma.sync.aligned.m16n8k8.row.col.f32.tf32.tf32.f32 "
        "{%0,%1,%2,%3}, {%4,%5,%6,%7}, {%8,%9}, {%0,%1,%2,%3};"
        : "+f"(c[0]), "+f"(c[1]), "+f"(c[2]), "+f"(c[3])
        : "r"(a[0]), "r"(a[1]), "r"(a[2]), "r"(a[3]), "r"(b0), "r"(b1));
}

__device__ __forceinline__ void mma_bf16_16x8x16(float c[4], const uint32_t a[4], uint32_t b0, uint32_t b1) {
    asm volatile(
        "mma.sync.aligned.m16n8k16.row.col.f32.bf16.bf16.f32 "
        "{%0,%1,%2,%3}, {%4,%5,%6,%7}, {%8,%9}, {%0,%1,%2,%3};"
        : "+f"(c[0]), "+f"(c[1]), "+f"(c[2]), "+f"(c[3])
        : "r"(a[0]), "r"(a[1]), "r"(a[2]), "r"(a[3]), "r"(b0), "r"(b1));
}

__device__ __forceinline__ uint32_t pack_bf2(float x, float y) {
    __nv_bfloat162 h = __float22bfloat162_rn(make_float2(x, y));
    return *(uint32_t*)&h;
}
__device__ __forceinline__ float bf2_lo_f32(uint32_t w) { return __uint_as_float(w << 16); }
__device__ __forceinline__ float bf2_hi_f32(uint32_t w) { return __uint_as_float(w & 0xffff0000u); }
__device__ __forceinline__ void split_bf2(float x, float y, uint32_t& hi, uint32_t& lo) {
    hi = pack_bf2(x, y);
    lo = pack_bf2(x - bf2_lo_f32(hi), y - bf2_hi_f32(hi));
}

__device__ __forceinline__ void cp16(void* dst, const void* src) {
    uint32_t s = (uint32_t)__cvta_generic_to_shared(dst);
    asm volatile("cp.async.cg.shared.global [%0], [%1], 16;" :: "r"(s), "l"(src));
}
__device__ __forceinline__ void cp_commit() { asm volatile("cp.async.commit_group;"); }
template<int N> __device__ __forceinline__ void cp_wait() { asm volatile("cp.async.wait_group %0;" :: "n"(N)); }

// ---------------------------------------------------------------------------
// Convert + permute:
//  A-perm (x, ctx): word w of [blk16 mb][k8 kb][lane]:
//      row = mb*16 + (lane>>2) + (w&1)*8,  col = kb*8 + (lane&3) + (w>>1)*4
//  B-perm (W):      word w of [n16 nb2][k8 kb][lane]:
//      n   = nb2*16 + (w>>1)*8 + (lane>>2), k = kb*8 + (lane&3) + (w&1)*4
// Each thread produces one 16B chunk (4 words).
// ---------------------------------------------------------------------------
#define XCHUNKS ((size_t)(NROWS/16)*KBLKS*32)   // 2^21
#define WCHUNKS ((size_t)NB2T*KBLKS*32)         // 2^20

__global__ void cvt_perm_kernel(const float* __restrict__ x,
                                const float* __restrict__ Wq,
                                const float* __restrict__ Wk,
                                const float* __restrict__ Wv,
                                const float* __restrict__ Wo)
{
    size_t idx = (size_t)blockIdx.x * 256 + threadIdx.x;
    const int lane = (int)(idx & 31);
    const int g = lane >> 2, tg = lane & 3;
    uint4 o;
    if (idx < XCHUNKS) {
        int kb = (int)((idx >> 5) & (KBLKS - 1));
        int mb = (int)(idx >> 13);
        const float* s = x + (size_t)(mb * 16 + g) * DMODEL + kb * 8 + tg;
        o.x = f32_to_tf32(s[0]);
        o.y = f32_to_tf32(s[8 * DMODEL]);
        o.z = f32_to_tf32(s[4]);
        o.w = f32_to_tf32(s[8 * DMODEL + 4]);
        ((uint4*)g_xp)[idx] = o;
    } else {
        size_t j = idx - XCHUNKS;
        int wsel = (int)(j >> 20);
        size_t o2 = j & ((((size_t)1) << 20) - 1);
        int kb = (int)((o2 >> 5) & (KBLKS - 1));
        int nb2 = (int)(o2 >> 13);
        const float* W = (wsel == 0) ? Wq : (wsel == 1) ? Wk : (wsel == 2) ? Wv : Wo;
        const float* s = W + (size_t)(nb2 * 16 + g) * DMODEL + kb * 8 + tg;
        o.x = f32_to_tf32(s[0]);
        o.y = f32_to_tf32(s[4]);
        o.z = f32_to_tf32(s[8 * DMODEL]);
        o.w = f32_to_tf32(s[8 * DMODEL + 4]);
        ((uint4*)g_wp)[(size_t)wsel * WCHUNKS + o2] = o;
    }
}

// ---------------------------------------------------------------------------
// tf32 NT GEMM on fragment-permuted operands, cp.async 3-stage pipeline.
// Block 128x256, BK=32, 256 threads = 8 warps (2x4), warp tile 64x64.
// All fragment loads are LDS.128.
// MODE 0: A=g_xp, z selects W, epilogue scatters f32 to g_q/g_k/g_v [b,h,t,dh]
// MODE 1: A=g_cp, W=Wo, adds bias, writes f32 row-major to Cout
// ---------------------------------------------------------------------------
#define ABYTES (8*4*32*16)     // 16384
#define BBYTES (16*4*32*16)    // 32768
#define STGB   (ABYTES + BBYTES)
#define NSTG 3
#define GEMM_SMEM (NSTG * STGB)   // 147456

template<int MODE>
__global__ void __launch_bounds__(256, 1) gemm_perm_kernel(
    const float* __restrict__ bias, float* __restrict__ Cout)
{
    extern __shared__ char sh[];

    const int tid  = threadIdx.x;
    const int lane = tid & 31;
    const int wrp  = tid >> 5;
    const int g    = lane >> 2;
    const int tg   = lane & 3;
    const int rh   = wrp >> 2;     // row-half 0/1 (64 rows each)
    const int cw   = wrp & 3;      // col-warp (64 cols each)

    const int rowBase = blockIdx.y * 128;
    const int colBase = blockIdx.x * 256;
    const int mb0  = blockIdx.y * 8;    // 8 m16 blocks
    const int nb20 = blockIdx.x * 16;   // 16 n16 blocks

    const uint32_t* Ag = (MODE == 0) ? g_xp : g_cp;
    const uint32_t* Bg = g_wp + (size_t)((MODE == 0) ? blockIdx.z : 3) * WSZ;
    float* dstQKV = nullptr;
    if (MODE == 0)
        dstQKV = (blockIdx.z == 0) ? g_q : (blockIdx.z == 1 ? g_k : g_v);

    auto issue = [&](int kt, int s) {
        char* st = sh + s * STGB;
        const int kb0 = kt * 4;
        #pragma unroll
        for (int p = 0; p < 4; p++) {              // A: 1024 chunks
            int c = tid + p * 256;
            int mbL = c >> 7, kbL = (c >> 5) & 3, ln = c & 31;
            const uint32_t* gsrc = Ag + (((size_t)(mb0 + mbL) * KBLKS + kb0 + kbL) * 32 + ln) * 4;
            cp16(st + c * 16, gsrc);
        }
        #pragma unroll
        for (int p = 0; p < 8; p++) {              // B: 2048 chunks
            int c = tid + p * 256;
            int nbL = c >> 7, kbL = (c >> 5) & 3, ln = c & 31;
            const uint32_t* gsrc = Bg + (((size_t)(nb20 + nbL) * KBLKS + kb0 + kbL) * 32 + ln) * 4;
            cp16(st + ABYTES + c * 16, gsrc);
        }
    };

    float acc[4][8][4];
    #pragma unroll
    for (int i = 0; i < 4; i++)
        #pragma unroll
        for (int j = 0; j < 8; j++)
            #pragma unroll
            for (int c = 0; c < 4; c++) acc[i][j][c] = 0.f;

    issue(0, 0); cp_commit();
    issue(1, 1); cp_commit();

    const int NKT = DMODEL / 32;   // 64
    for (int kt = 0; kt < NKT; kt++) {
        cp_wait<1>();
        __syncthreads();
        if (kt + 2 < NKT) issue(kt + 2, (kt + 2) % NSTG);
        cp_commit();

        const char* st = sh + (kt % NSTG) * STGB;
        const uint4* As4 = (const uint4*)st;
        const uint4* Bs4 = (const uint4*)(st + ABYTES);

        #pragma unroll
        for (int kk = 0; kk < 4; kk++) {
            uint4 af[4];
            #pragma unroll
            for (int i = 0; i < 4; i++)
                af[i] = As4[((rh * 4 + i) * 4 + kk) * 32 + lane];
            #pragma unroll
            for (int j2 = 0; j2 < 4; j2++) {
                uint4 bv = Bs4[((cw * 4 + j2) * 4 + kk) * 32 + lane];
                #pragma unroll
                for (int i = 0; i < 4; i++) {
                    mma_tf32_16x8x8(acc[i][2*j2  ], (const uint32_t*)&af[i], bv.x, bv.y);
                    mma_tf32_16x8x8(acc[i][2*j2+1], (const uint32_t*)&af[i], bv.z, bv.w);
                }
            }
        }
    }

    if (MODE == 0) {
        #pragma unroll
        for (int i = 0; i < 4; i++) {
            #pragma unroll
            for (int cc = 0; cc < 2; cc++) {
                int m = rowBase + rh * 64 + i * 16 + g + cc * 8;
                int b = m >> 11;
                int t = m & (SEQ - 1);
                size_t rowoff = ((size_t)(b * NHEADS) * SEQ + t) << 7;
                #pragma unroll
                for (int j = 0; j < 8; j++) {
                    int n0 = colBase + cw * 64 + j * 8 + tg * 2;
                    int h  = n0 >> 7;
                    int dh = n0 & (HDIM - 1);
                    float* dst = dstQKV + rowoff + (((size_t)h * SEQ) << 7) + dh;
                    dst[0] = acc[i][j][cc * 2 + 0];
                    dst[1] = acc[i][j][cc * 2 + 1];
                }
            }
        }
    } else {
        #pragma unroll
        for (int i = 0; i < 4; i++) {
            #pragma unroll
            for (int cc = 0; cc < 2; cc++) {
                int m = rowBase + rh * 64 + i * 16 + g + cc * 8;
                #pragma unroll
                for (int j = 0; j < 8; j++) {
                    int n0 = colBase + cw * 64 + j * 8 + tg * 2;
                    float2 v;
                    v.x = acc[i][j][cc * 2 + 0] + bias[n0];
                    v.y = acc[i][j][cc * 2 + 1] + bias[n0 + 1];
                    *(float2*)(Cout + (size_t)m * DMODEL + n0) = v;
                }
            }
        }
    }
}

// ---------------------------------------------------------------------------
// RoPE in-place on g_q / g_k (unchanged).
// ---------------------------------------------------------------------------
__global__ void rope_kernel(const float* __restrict__ theta)
{
    int d = threadIdx.x;
    int t = blockIdx.x * 4 + threadIdx.y;
    int bh = blockIdx.y;
    float* buf = blockIdx.z ? g_k : g_q;
    float* row = buf + ((size_t)bh * SEQ + t) * HDIM;

    float ve = row[2*d];
    float vo = row[2*d+1];
    float f = (float)t * theta[d];
    float s, c;
    sincosf(f, &s, &c);
    __syncthreads();
    row[d]      = ve * c - vo * s;
    row[64 + d] = ve * s + vo * c;
}

// ---------------------------------------------------------------------------
// Tensor-core flash attention (bf16x3), causal.
// Epilogue writes ctx as tf32 bits in A-fragment-permuted layout (g_cp).
// ---------------------------------------------------------------------------
#define Q_STRIDE 68
#define V_STRIDE 36
#define SM_QHI 0
#define SM_QLO (SM_QHI + 128*Q_STRIDE)
#define SM_KHI (SM_QLO + 128*Q_STRIDE)
#define SM_KLO (SM_KHI + 64*Q_STRIDE)
#define SM_VHI (SM_KLO + 64*Q_STRIDE)
#define SM_VLO (SM_VHI + 128*V_STRIDE)
#define ATTN_SMEM_WORDS (SM_VLO + 128*V_STRIDE)

__global__ void __launch_bounds__(256, 1) attn_bf16_kernel()
{
    extern __shared__ uint32_t sm[];
    uint32_t* Qhi = sm + SM_QHI;
    uint32_t* Qlo = sm + SM_QLO;
    uint32_t* Khi = sm + SM_KHI;
    uint32_t* Klo = sm + SM_KLO;
    uint32_t* Vhi = sm + SM_VHI;
    uint32_t* Vlo = sm + SM_VLO;

    const int tid  = threadIdx.x;
    const int lane = tid & 31;
    const int wrp  = tid >> 5;
    const int g    = lane >> 2;
    const int tg   = lane & 3;
    const int wr   = wrp * 16;

    const int qt = gridDim.x - 1 - blockIdx.x;   // big tiles first
    const int bh = blockIdx.y;
    const int qs = qt * 128;
    const size_t base = (size_t)bh * SEQ * HDIM;
    const float scale = 0.08838834764831845f;

    #pragma unroll
    for (int p = 0; p < 16; p++) {
        int idx = tid + p * 256;
        int r   = idx >> 5;
        int c4  = idx & 31;
        float4 v = *(const float4*)(g_q + base + (size_t)(qs + r) * HDIM + c4 * 4);
        uint32_t h0, l0, h1, l1;
        split_bf2(v.x, v.y, h0, l0);
        split_bf2(v.z, v.w, h1, l1);
        Qhi[r * Q_STRIDE + c4*2    ] = h0;
        Qhi[r * Q_STRIDE + c4*2 + 1] = h1;
        Qlo[r * Q_STRIDE + c4*2    ] = l0;
        Qlo[r * Q_STRIDE + c4*2 + 1] = l1;
    }

    float o[16][4];
    #pragma unroll
    for (int j = 0; j < 16; j++)
        #pragma unroll
        for (int c = 0; c < 4; c++) o[j][c] = 0.f;
    float m0 = -INFINITY, m1 = -INFINITY, l0s = 0.f, l1s = 0.f;

    const int ktiles = 2 * qt + 2;
    for (int kt = 0; kt < ktiles; kt++) {
        const int ks = kt * 64;
        __syncthreads();

        #pragma unroll
        for (int p = 0; p < 8; p++) {
            int idx = tid + p * 256;
            int r   = idx >> 5;
            int c4  = idx & 31;
            float4 v = *(const float4*)(g_k + base + (size_t)(ks + r) * HDIM + c4 * 4);
            uint32_t h0, l0, h1, l1;
            split_bf2(v.x, v.y, h0, l0);
            split_bf2(v.z, v.w, h1, l1);
            Khi[r * Q_STRIDE + c4*2    ] = h0;
            Khi[r * Q_STRIDE + c4*2 + 1] = h1;
            Klo[r * Q_STRIDE + c4*2    ] = l0;
            Klo[r * Q_STRIDE + c4*2 + 1] = l1;
        }
        #pragma unroll
        for (int p = 0; p < 4; p++) {
            int u  = tid + p * 256;
            int m2 = u & 31;
            int d0 = (u >> 5) * 4;
            float4 va = *(const float4*)(g_v + base + (size_t)(ks + 2*m2    ) * HDIM + d0);
            float4 vb = *(const float4*)(g_v + base + (size_t)(ks + 2*m2 + 1) * HDIM + d0);
            const float* pa = &va.x;
            const float* pb = &vb.x;
            #pragma unroll
            for (int i = 0; i < 4; i++) {
                uint32_t h, l;
                split_bf2(pa[i], pb[i], h, l);
                Vhi[(d0 + i) * V_STRIDE + m2] = h;
                Vlo[(d0 + i) * V_STRIDE + m2] = l;
            }
        }
        __syncthreads();

        float sc[8][4];
        #pragma unroll
        for (int j = 0; j < 8; j++)
            #pragma unroll
            for (int c = 0; c < 4; c++) sc[j][c] = 0.f;

        const int ra0 = (wr + g) * Q_STRIDE;
        const int ra1 = (wr + g + 8) * Q_STRIDE;
        #pragma unroll
        for (int kk = 0; kk < 8; kk++) {
            const int kw = kk * 8;
            uint32_t ah[4], al[4];
            ah[0] = Qhi[ra0 + kw + tg];     al[0] = Qlo[ra0 + kw + tg];
            ah[1] = Qhi[ra1 + kw + tg];     al[1] = Qlo[ra1 + kw + tg];
            ah[2] = Qhi[ra0 + kw + tg + 4]; al[2] = Qlo[ra0 + kw + tg + 4];
            ah[3] = Qhi[ra1 + kw + tg + 4]; al[3] = Qlo[ra1 + kw + tg + 4];
            #pragma unroll
            for (int j = 0; j < 8; j++) {
                const int rb = (j * 8 + g) * Q_STRIDE + kw;
                uint32_t bh0 = Khi[rb + tg], bh1 = Khi[rb + tg + 4];
                uint32_t bl0 = Klo[rb + tg], bl1 = Klo[rb + tg + 4];
                mma_bf16_16x8x16(sc[j], ah, bh0, bh1);
                mma_bf16_16x8x16(sc[j], ah, bl0, bl1);
                mma_bf16_16x8x16(sc[j], al, bh0, bh1);
            }
        }

        const int r0 = qs + wr + g;
        const int r1 = r0 + 8;
        const bool part = (ks + 63 > qs + wr);
        #pragma unroll
        for (int j = 0; j < 8; j++) {
            int cb = ks + j * 8 + 2 * tg;
            sc[j][0] = (part && cb     > r0) ? -1e30f : sc[j][0] * scale;
            sc[j][1] = (part && cb + 1 > r0) ? -1e30f : sc[j][1] * scale;
            sc[j][2] = (part && cb     > r1) ? -1e30f : sc[j][2] * scale;
            sc[j][3] = (part && cb + 1 > r1) ? -1e30f : sc[j][3] * scale;
        }

        float mx0 = -INFINITY, mx1 = -INFINITY;
        #pragma unroll
        for (int j = 0; j < 8; j++) {
            mx0 = fmaxf(mx0, fmaxf(sc[j][0], sc[j][1]));
            mx1 = fmaxf(mx1, fmaxf(sc[j][2], sc[j][3]));
        }
        mx0 = fmaxf(mx0, __shfl_xor_sync(0xffffffff, mx0, 1));
        mx0 = fmaxf(mx0, __shfl_xor_sync(0xffffffff, mx0, 2));
        mx1 = fmaxf(mx1, __shfl_xor_sync(0xffffffff, mx1, 1));
        mx1 = fmaxf(mx1, __shfl_xor_sync(0xffffffff, mx1, 2));

        float nm0 = fmaxf(m0, mx0);
        float nm1 = fmaxf(m1, mx1);
        float fac0 = __expf(m0 - nm0);
        float fac1 = __expf(m1 - nm1);
        m0 = nm0; m1 = nm1;

        float sum0 = 0.f, sum1 = 0.f;
        #pragma unroll
        for (int j = 0; j < 8; j++) {
            sc[j][0] = __expf(sc[j][0] - m0); sum0 += sc[j][0];
            sc[j][1] = __expf(sc[j][1] - m0); sum0 += sc[j][1];
            sc[j][2] = __expf(sc[j][2] - m1); sum1 += sc[j][2];
            sc[j][3] = __expf(sc[j][3] - m1); sum1 += sc[j][3];
        }
        sum0 += __shfl_xor_sync(0xffffffff, sum0, 1);
        sum0 += __shfl_xor_sync(0xffffffff, sum0, 2);
        sum1 += __shfl_xor_sync(0xffffffff, sum1, 1);
        sum1 += __shfl_xor_sync(0xffffffff, sum1, 2);
        l0s = l0s * fac0 + sum0;
        l1s = l1s * fac1 + sum1;

        #pragma unroll
        for (int j = 0; j < 16; j++) {
            o[j][0] *= fac0; o[j][1] *= fac0;
            o[j][2] *= fac1; o[j][3] *= fac1;
        }

        #pragma unroll
        for (int k2 = 0; k2 < 4; k2++) {
            uint32_t ah[4], al[4];
            split_bf2(sc[2*k2  ][0], sc[2*k2  ][1], ah[0], al[0]);
            split_bf2(sc[2*k2  ][2], sc[2*k2  ][3], ah[1], al[1]);
            split_bf2(sc[2*k2+1][0], sc[2*k2+1][1], ah[2], al[2]);
            split_bf2(sc[2*k2+1][2], sc[2*k2+1][3], ah[3], al[3]);
            #pragma unroll
            for (int jd = 0; jd < 16; jd++) {
                const int rb = (jd * 8 + g) * V_STRIDE + k2 * 8;
                uint32_t bh0 = Vhi[rb + tg], bh1 = Vhi[rb + tg + 4];
                uint32_t bl0 = Vlo[rb + tg], bl1 = Vlo[rb + tg + 4];
                mma_bf16_16x8x16(o[jd], ah, bh0, bh1);
                mma_bf16_16x8x16(o[jd], ah, bl0, bl1);
                mma_bf16_16x8x16(o[jd], al, bh0, bh1);
            }
        }
    }

    // ---- epilogue: ctx -> g_cp (tf32 bits, A-fragment-permuted) ----
    // C-frag (row g / g+8, cols 2tg, 2tg+1) maps to perm words:
    //   lane' = 4g + ((tg&1)*2) (+1 for col+1), words (tg>>1)*2 and +1 (row, row+8)
    const float inv0 = 1.f / l0s;
    const float inv1 = 1.f / l1s;
    const int b = bh >> 4;
    const int h = bh & 15;
    const int m_blk = (b * SEQ + qs + wr) >> 4;     // all multiples of 16
    const int lane0 = 4 * g + (tg & 1) * 2;
    const int w0 = (tg >> 1) * 2;
    #pragma unroll
    for (int jd = 0; jd < 16; jd++) {
        int kblk = h * 16 + jd;
        uint32_t* p = g_cp + (((size_t)m_blk * KBLKS + kblk) * 32 + lane0) * 4 + w0;
        *(uint2*)p       = make_uint2(f32_to_tf32(o[jd][0] * inv0), f32_to_tf32(o[jd][2] * inv1));
        *(uint2*)(p + 4) = make_uint2(f32_to_tf32(o[jd][1] * inv0), f32_to_tf32(o[jd][3] * inv1));
    }
}

// ---------------------------------------------------------------------------
extern "C" void kernel_launch(void* const* d_in, const int* in_sizes, int n_in,
                              void* d_out, int out_size)
{
    const float* x     = (const float*)d_in[0];
    const float* Wq    = (const float*)d_in[1];
    const float* Wk    = (const float*)d_in[2];
    const float* Wv    = (const float*)d_in[3];
    const float* Wo    = (const float*)d_in[4];
    const float* bo    = (const float*)d_in[5];
    const float* theta = (const float*)d_in[6];
    float* out = (float*)d_out;

    // 0. Convert + permute x and weights to tf32 fragment layout
    const size_t total_chunks = XCHUNKS + 4 * WCHUNKS;
    cvt_perm_kernel<<<(unsigned)(total_chunks / 256), 256>>>(x, Wq, Wk, Wv, Wo);

    // 1. QKV projections, scatter to [b,h,t,dh]
    cudaFuncSetAttribute(gemm_perm_kernel<0>, cudaFuncAttributeMaxDynamicSharedMemorySize, GEMM_SMEM);
    gemm_perm_kernel<0><<<dim3(DMODEL/256, NROWS/128, 3), 256, GEMM_SMEM>>>(nullptr, nullptr);

    // 2. RoPE on q and k
    rope_kernel<<<dim3(SEQ/4, BSZ*NHEADS, 2), dim3(64, 4)>>>(theta);

    // 3. Causal flash attention (bf16x3), emits permuted tf32 ctx
    const int attn_smem = ATTN_SMEM_WORDS * (int)sizeof(uint32_t);
    cudaFuncSetAttribute(attn_bf16_kernel, cudaFuncAttributeMaxDynamicSharedMemorySize, attn_smem);
    attn_bf16_kernel<<<dim3(SEQ/128, BSZ*NHEADS), 256, attn_smem>>>();

    // 4. Output projection + bias
    cudaFuncSetAttribute(gemm_perm_kernel<1>, cudaFuncAttributeMaxDynamicSharedMemorySize, GEMM_SMEM);
    gemm_perm_kernel<1><<<dim3(DMODEL/256, NROWS/128, 1), 256, GEMM_SMEM>>>(bo, out);
}

// round 8
// speedup vs baseline: 4.7823x; 1.0799x over previous
#include <cuda_runtime.h>
#include <cuda_bf16.h>
#include <math.h>
#include <stdint.h>

#define BSZ 2
#define SEQ 2048
#define DMODEL 2048
#define NHEADS 16
#define HDIM 128
#define NROWS (BSZ*SEQ)     // 4096
#define WSZ (DMODEL*DMODEL)
#define KBLKS (DMODEL/8)    // 256 k8-blocks per row
#define NB2T (DMODEL/16)    // 128 n16-blocks

// Scratch (allocation-free rule: __device__ globals)
__device__ float    g_q[BSZ*NHEADS*SEQ*HDIM];
__device__ float    g_k[BSZ*NHEADS*SEQ*HDIM];
__device__ float    g_v[BSZ*NHEADS*SEQ*HDIM];
__device__ uint32_t g_xp[(size_t)NROWS*DMODEL];   // x, tf32 bits, A-fragment-permuted
__device__ uint32_t g_wp[(size_t)4*WSZ];          // Wq,Wk,Wv,Wo tf32 bits, B-fragment-permuted
__device__ uint32_t g_cp[(size_t)NROWS*DMODEL];   // ctx, tf32 bits, A-fragment-permuted
// attention operands, pre-split bf16 hi/lo packed words
__device__ uint32_t g_qh[(size_t)BSZ*NHEADS*SEQ*64];
__device__ uint32_t g_ql[(size_t)BSZ*NHEADS*SEQ*64];
__device__ uint32_t g_kh[(size_t)BSZ*NHEADS*SEQ*64];
__device__ uint32_t g_kl[(size_t)BSZ*NHEADS*SEQ*64];
__device__ uint32_t g_vth[(size_t)BSZ*NHEADS*HDIM*(SEQ/2)];   // [bh][d][tpair]
__device__ uint32_t g_vtl[(size_t)BSZ*NHEADS*HDIM*(SEQ/2)];

// ---------------------------------------------------------------------------
// helpers
// ---------------------------------------------------------------------------
__device__ __forceinline__ uint32_t f32_to_tf32(float f) {
    uint32_t r;
    asm("cvt.rna.tf32.f32 %0, %1;" : "=r"(r) : "f"(f));
    return r;
}

__device__ __forceinline__ void mma_tf32_16x8x8(float c[4], const uint32_t a[4], uint32_t b0, uint32_t b1) {
    asm volatile(
        "mma.sync.aligned.m16n8k8.row.col.f32.tf32.tf32.f32 "
        "{%0,%1,%2,%3}, {%4,%5,%6,%7}, {%8,%9}, {%0,%1,%2,%3};"
        : "+f"(c[0]), "+f"(c[1]), "+f"(c[2]), "+f"(c[3])
        : "r"(a[0]), "r"(a[1]), "r"(a[2]), "r"(a[3]), "r"(b0), "r"(b1));
}

__device__ __forceinline__ void mma_bf16_16x8x16(float c[4], const uint32_t a[4], uint32_t b0, uint32_t b1) {
    asm volatile(
        "mma.sync.aligned.m16n8k16.row.col.f32.bf16.bf16.f32 "
        "{%0,%1,%2,%3}, {%4,%5,%6,%7}, {%8,%9}, {%0,%1,%2,%3};"
        : "+f"(c[0]), "+f"(c[1]), "+f"(c[2]), "+f"(c[3])
        : "r"(a[0]), "r"(a[1]), "r"(a[2]), "r"(a[3]), "r"(b0), "r"(b1));
}

__device__ __forceinline__ uint32_t pack_bf2(float x, float y) {
    __nv_bfloat162 h = __float22bfloat162_rn(make_float2(x, y));
    return *(uint32_t*)&h;
}
__device__ __forceinline__ float bf2_lo_f32(uint32_t w) { return __uint_as_float(w << 16); }
__device__ __forceinline__ float bf2_hi_f32(uint32_t w) { return __uint_as_float(w & 0xffff0000u); }
__device__ __forceinline__ void split_bf2(float x, float y, uint32_t& hi, uint32_t& lo) {
    hi = pack_bf2(x, y);
    lo = pack_bf2(x - bf2_lo_f32(hi), y - bf2_hi_f32(hi));
}

__device__ __forceinline__ void cp16(void* dst, const void* src) {
    uint32_t s = (uint32_t)__cvta_generic_to_shared(dst);
    asm volatile("cp.async.cg.shared.global [%0], [%1], 16;" :: "r"(s), "l"(src));
}
__device__ __forceinline__ void cp_commit() { asm volatile("cp.async.commit_group;"); }
template<int N> __device__ __forceinline__ void cp_wait() { asm volatile("cp.async.wait_group %0;" :: "n"(N)); }

// ---------------------------------------------------------------------------
// Convert + permute x / weights to tf32 fragment layout (unchanged from R7)
// ---------------------------------------------------------------------------
#define XCHUNKS ((size_t)(NROWS/16)*KBLKS*32)   // 2^21
#define WCHUNKS ((size_t)NB2T*KBLKS*32)         // 2^20

__global__ void cvt_perm_kernel(const float* __restrict__ x,
                                const float* __restrict__ Wq,
                                const float* __restrict__ Wk,
                                const float* __restrict__ Wv,
                                const float* __restrict__ Wo)
{
    size_t idx = (size_t)blockIdx.x * 256 + threadIdx.x;
    const int lane = (int)(idx & 31);
    const int g = lane >> 2, tg = lane & 3;
    uint4 o;
    if (idx < XCHUNKS) {
        int kb = (int)((idx >> 5) & (KBLKS - 1));
        int mb = (int)(idx >> 13);
        const float* s = x + (size_t)(mb * 16 + g) * DMODEL + kb * 8 + tg;
        o.x = f32_to_tf32(s[0]);
        o.y = f32_to_tf32(s[8 * DMODEL]);
        o.z = f32_to_tf32(s[4]);
        o.w = f32_to_tf32(s[8 * DMODEL + 4]);
        ((uint4*)g_xp)[idx] = o;
    } else {
        size_t j = idx - XCHUNKS;
        int wsel = (int)(j >> 20);
        size_t o2 = j & ((((size_t)1) << 20) - 1);
        int kb = (int)((o2 >> 5) & (KBLKS - 1));
        int nb2 = (int)(o2 >> 13);
        const float* W = (wsel == 0) ? Wq : (wsel == 1) ? Wk : (wsel == 2) ? Wv : Wo;
        const float* s = W + (size_t)(nb2 * 16 + g) * DMODEL + kb * 8 + tg;
        o.x = f32_to_tf32(s[0]);
        o.y = f32_to_tf32(s[4]);
        o.z = f32_to_tf32(s[8 * DMODEL]);
        o.w = f32_to_tf32(s[8 * DMODEL + 4]);
        ((uint4*)g_wp)[(size_t)wsel * WCHUNKS + o2] = o;
    }
}

// ---------------------------------------------------------------------------
// tf32 NT GEMM on fragment-permuted operands (unchanged from R7)
// ---------------------------------------------------------------------------
#define ABYTES (8*4*32*16)     // 16384
#define BBYTES (16*4*32*16)    // 32768
#define STGB   (ABYTES + BBYTES)
#define NSTG 3
#define GEMM_SMEM (NSTG * STGB)   // 147456

template<int MODE>
__global__ void __launch_bounds__(256, 1) gemm_perm_kernel(
    const float* __restrict__ bias, float* __restrict__ Cout)
{
    extern __shared__ char sh[];

    const int tid  = threadIdx.x;
    const int lane = tid & 31;
    const int wrp  = tid >> 5;
    const int g    = lane >> 2;
    const int tg   = lane & 3;
    const int rh   = wrp >> 2;
    const int cw   = wrp & 3;

    const int rowBase = blockIdx.y * 128;
    const int colBase = blockIdx.x * 256;
    const int mb0  = blockIdx.y * 8;
    const int nb20 = blockIdx.x * 16;

    const uint32_t* Ag = (MODE == 0) ? g_xp : g_cp;
    const uint32_t* Bg = g_wp + (size_t)((MODE == 0) ? blockIdx.z : 3) * WSZ;
    float* dstQKV = nullptr;
    if (MODE == 0)
        dstQKV = (blockIdx.z == 0) ? g_q : (blockIdx.z == 1 ? g_k : g_v);

    auto issue = [&](int kt, int s) {
        char* st = sh + s * STGB;
        const int kb0 = kt * 4;
        #pragma unroll
        for (int p = 0; p < 4; p++) {
            int c = tid + p * 256;
            int mbL = c >> 7, kbL = (c >> 5) & 3, ln = c & 31;
            const uint32_t* gsrc = Ag + (((size_t)(mb0 + mbL) * KBLKS + kb0 + kbL) * 32 + ln) * 4;
            cp16(st + c * 16, gsrc);
        }
        #pragma unroll
        for (int p = 0; p < 8; p++) {
            int c = tid + p * 256;
            int nbL = c >> 7, kbL = (c >> 5) & 3, ln = c & 31;
            const uint32_t* gsrc = Bg + (((size_t)(nb20 + nbL) * KBLKS + kb0 + kbL) * 32 + ln) * 4;
            cp16(st + ABYTES + c * 16, gsrc);
        }
    };

    float acc[4][8][4];
    #pragma unroll
    for (int i = 0; i < 4; i++)
        #pragma unroll
        for (int j = 0; j < 8; j++)
            #pragma unroll
            for (int c = 0; c < 4; c++) acc[i][j][c] = 0.f;

    issue(0, 0); cp_commit();
    issue(1, 1); cp_commit();

    const int NKT = DMODEL / 32;
    for (int kt = 0; kt < NKT; kt++) {
        cp_wait<1>();
        __syncthreads();
        if (kt + 2 < NKT) issue(kt + 2, (kt + 2) % NSTG);
        cp_commit();

        const char* st = sh + (kt % NSTG) * STGB;
        const uint4* As4 = (const uint4*)st;
        const uint4* Bs4 = (const uint4*)(st + ABYTES);

        #pragma unroll
        for (int kk = 0; kk < 4; kk++) {
            uint4 af[4];
            #pragma unroll
            for (int i = 0; i < 4; i++)
                af[i] = As4[((rh * 4 + i) * 4 + kk) * 32 + lane];
            #pragma unroll
            for (int j2 = 0; j2 < 4; j2++) {
                uint4 bv = Bs4[((cw * 4 + j2) * 4 + kk) * 32 + lane];
                #pragma unroll
                for (int i = 0; i < 4; i++) {
                    mma_tf32_16x8x8(acc[i][2*j2  ], (const uint32_t*)&af[i], bv.x, bv.y);
                    mma_tf32_16x8x8(acc[i][2*j2+1], (const uint32_t*)&af[i], bv.z, bv.w);
                }
            }
        }
    }

    if (MODE == 0) {
        #pragma unroll
        for (int i = 0; i < 4; i++) {
            #pragma unroll
            for (int cc = 0; cc < 2; cc++) {
                int m = rowBase + rh * 64 + i * 16 + g + cc * 8;
                int b = m >> 11;
                int t = m & (SEQ - 1);
                size_t rowoff = ((size_t)(b * NHEADS) * SEQ + t) << 7;
                #pragma unroll
                for (int j = 0; j < 8; j++) {
                    int n0 = colBase + cw * 64 + j * 8 + tg * 2;
                    int h  = n0 >> 7;
                    int dh = n0 & (HDIM - 1);
                    float* dst = dstQKV + rowoff + (((size_t)h * SEQ) << 7) + dh;
                    dst[0] = acc[i][j][cc * 2 + 0];
                    dst[1] = acc[i][j][cc * 2 + 1];
                }
            }
        }
    } else {
        #pragma unroll
        for (int i = 0; i < 4; i++) {
            #pragma unroll
            for (int cc = 0; cc < 2; cc++) {
                int m = rowBase + rh * 64 + i * 16 + g + cc * 8;
                #pragma unroll
                for (int j = 0; j < 8; j++) {
                    int n0 = colBase + cw * 64 + j * 8 + tg * 2;
                    float2 v;
                    v.x = acc[i][j][cc * 2 + 0] + bias[n0];
                    v.y = acc[i][j][cc * 2 + 1] + bias[n0 + 1];
                    *(float2*)(Cout + (size_t)m * DMODEL + n0) = v;
                }
            }
        }
    }
}

// ---------------------------------------------------------------------------
// RoPE: reads f32 g_q/g_k rows, emits packed bf16 hi/lo words directly.
// Thread j (0..63): j<32 -> word j = pair(out[2j], out[2j+1]) of first half;
// j>=32 -> word j = pair(out[64+2j'], out[64+2j'+1]), j'=j-32.
// Bit-identical values to splitting after an f32 rope.
// ---------------------------------------------------------------------------
__global__ void rope_split_kernel(const float* __restrict__ theta)
{
    const int j  = threadIdx.x;                    // 0..63
    const int t  = blockIdx.x * 4 + threadIdx.y;
    const int bh = blockIdx.y;
    const bool isK = blockIdx.z != 0;
    const int jj = j & 31;

    const float* row = (isK ? g_k : g_q) + ((size_t)bh * SEQ + t) * HDIM;
    float4 v = *(const float4*)(row + 4 * jj);
    float th0 = theta[2*jj], th1 = theta[2*jj + 1];
    float s0, c0, s1, c1;
    sincosf((float)t * th0, &s0, &c0);
    sincosf((float)t * th1, &s1, &c1);

    float o0, o1;
    if (j < 32) { o0 = v.x * c0 - v.y * s0;  o1 = v.z * c1 - v.w * s1; }
    else        { o0 = v.x * s0 + v.y * c0;  o1 = v.z * s1 + v.w * c1; }

    uint32_t hi, lo;
    split_bf2(o0, o1, hi, lo);
    size_t woff = ((size_t)bh * SEQ + t) * 64 + j;
    (isK ? g_kh : g_qh)[woff] = hi;
    (isK ? g_kl : g_ql)[woff] = lo;
}

// ---------------------------------------------------------------------------
// V prep: transpose + split V once globally.  g_v [bh][t][d] f32 ->
// g_vth/g_vtl [bh][d][tpair] packed bf16 words (pair = t even/odd).
// Block: 128 t x 32 d tile; grid (SEQ/128, HDIM/32, BSZ*NHEADS).
// ---------------------------------------------------------------------------
__global__ void __launch_bounds__(256) v_prep_kernel()
{
    __shared__ float sm[128 * 37];
    const int tid = threadIdx.x;
    const int t0 = blockIdx.x * 128;
    const int d0 = blockIdx.y * 32;
    const int bh = blockIdx.z;
    const float* src = g_v + ((size_t)bh * SEQ + t0) * HDIM + d0;

    #pragma unroll
    for (int p = 0; p < 4; p++) {
        int c = tid + p * 256;          // 0..1023 float4s
        int t = c >> 3;                  // 0..127
        int q = (c & 7) * 4;             // 0..28
        float4 v = *(const float4*)(src + (size_t)t * HDIM + q);
        float* d = sm + t * 37 + q;
        d[0] = v.x; d[1] = v.y; d[2] = v.z; d[3] = v.w;
    }
    __syncthreads();

    uint32_t* dh = g_vth + ((size_t)bh * HDIM + d0) * (SEQ/2) + t0 / 2;
    uint32_t* dl = g_vtl + ((size_t)bh * HDIM + d0) * (SEQ/2) + t0 / 2;
    #pragma unroll
    for (int p = 0; p < 8; p++) {
        int w = tid + p * 256;          // 0..2047
        int d = w >> 6;                  // 0..31
        int tp = w & 63;                 // 0..63
        uint32_t hi, lo;
        split_bf2(sm[(2*tp) * 37 + d], sm[(2*tp + 1) * 37 + d], hi, lo);
        dh[(size_t)d * (SEQ/2) + tp] = hi;
        dl[(size_t)d * (SEQ/2) + tp] = lo;
    }
}

// ---------------------------------------------------------------------------
// Tensor-core flash attention (bf16x3), causal. Pre-split operands,
// cp.async double-buffered K/V. Epilogue -> g_cp (permuted tf32 ctx).
// smem layout (words): Q hi/lo [128][68]; per stage: K hi/lo [64][68],
// V hi/lo [128][36]. 2 stages. Total 53248 words = 212992 B.
// ---------------------------------------------------------------------------
#define AQHI 0
#define AQLO 8704
#define AST0 17408
#define ASTSZ 17920
#define AKHI 0
#define AKLO 4352
#define AVHI 8704
#define AVLO 13312
#define ATTN_SMEM_BYTES ((AST0 + 2*ASTSZ) * 4)

__global__ void __launch_bounds__(256, 1) attn_bf16_kernel()
{
    extern __shared__ uint32_t sm[];

    const int tid  = threadIdx.x;
    const int lane = tid & 31;
    const int wrp  = tid >> 5;
    const int g    = lane >> 2;
    const int tg   = lane & 3;
    const int wr   = wrp * 16;

    const int qt = gridDim.x - 1 - blockIdx.x;   // big tiles first
    const int bh = blockIdx.y;
    const int qs = qt * 128;
    const size_t wbase = (size_t)bh * SEQ * 64;          // q/k word base
    const size_t vbase = (size_t)bh * HDIM * (SEQ/2);    // v word base
    const float scale = 0.08838834764831845f;
    const int ktiles = 2 * qt + 2;

    auto issueKV = [&](int kt) {
        if (kt >= ktiles) return;
        uint32_t* st = sm + AST0 + (kt & 1) * ASTSZ;
        const int ks = kt * 64;
        #pragma unroll
        for (int p = 0; p < 4; p++) {                  // K: 64 rows x 16 chunks
            int c = tid + p * 256;                     // 0..1023
            int r = c >> 4, q4 = (c & 15) * 4;
            cp16(st + AKHI + r * 68 + q4, g_kh + wbase + (size_t)(ks + r) * 64 + q4);
            cp16(st + AKLO + r * 68 + q4, g_kl + wbase + (size_t)(ks + r) * 64 + q4);
        }
        #pragma unroll
        for (int p = 0; p < 4; p++) {                  // V: 128 d x 8 chunks
            int c = tid + p * 256;                     // 0..1023
            int d = c >> 3, q4 = (c & 7) * 4;
            cp16(st + AVHI + d * 36 + q4, g_vth + vbase + (size_t)d * (SEQ/2) + kt * 32 + q4);
            cp16(st + AVLO + d * 36 + q4, g_vtl + vbase + (size_t)d * (SEQ/2) + kt * 32 + q4);
        }
    };

    // Q load (once) + stage 0, then stage 1
    #pragma unroll
    for (int p = 0; p < 8; p++) {
        int c = tid + p * 256;                         // 0..2047
        int r = c >> 4, q4 = (c & 15) * 4;
        cp16(sm + AQHI + r * 68 + q4, g_qh + wbase + (size_t)(qs + r) * 64 + q4);
        cp16(sm + AQLO + r * 68 + q4, g_ql + wbase + (size_t)(qs + r) * 64 + q4);
    }
    issueKV(0); cp_commit();
    issueKV(1); cp_commit();

    float o[16][4];
    #pragma unroll
    for (int j = 0; j < 16; j++)
        #pragma unroll
        for (int c = 0; c < 4; c++) o[j][c] = 0.f;
    float m0 = -INFINITY, m1 = -INFINITY, l0s = 0.f, l1s = 0.f;

    for (int kt = 0; kt < ktiles; kt++) {
        const int ks = kt * 64;
        cp_wait<1>();
        __syncthreads();

        const uint32_t* Khi = sm + AST0 + (kt & 1) * ASTSZ + AKHI;
        const uint32_t* Klo = sm + AST0 + (kt & 1) * ASTSZ + AKLO;
        const uint32_t* Vhi = sm + AST0 + (kt & 1) * ASTSZ + AVHI;
        const uint32_t* Vlo = sm + AST0 + (kt & 1) * ASTSZ + AVLO;
        const uint32_t* Qhi = sm + AQHI;
        const uint32_t* Qlo = sm + AQLO;

        float sc[8][4];
        #pragma unroll
        for (int j = 0; j < 8; j++)
            #pragma unroll
            for (int c = 0; c < 4; c++) sc[j][c] = 0.f;

        const int ra0 = (wr + g) * 68;
        const int ra1 = (wr + g + 8) * 68;
        #pragma unroll
        for (int kk = 0; kk < 8; kk++) {
            const int kw = kk * 8;
            uint32_t ah[4], al[4];
            ah[0] = Qhi[ra0 + kw + tg];     al[0] = Qlo[ra0 + kw + tg];
            ah[1] = Qhi[ra1 + kw + tg];     al[1] = Qlo[ra1 + kw + tg];
            ah[2] = Qhi[ra0 + kw + tg + 4]; al[2] = Qlo[ra0 + kw + tg + 4];
            ah[3] = Qhi[ra1 + kw + tg + 4]; al[3] = Qlo[ra1 + kw + tg + 4];
            #pragma unroll
            for (int j = 0; j < 8; j++) {
                const int rb = (j * 8 + g) * 68 + kw;
                uint32_t bh0 = Khi[rb + tg], bh1 = Khi[rb + tg + 4];
                uint32_t bl0 = Klo[rb + tg], bl1 = Klo[rb + tg + 4];
                mma_bf16_16x8x16(sc[j], ah, bh0, bh1);
                mma_bf16_16x8x16(sc[j], ah, bl0, bl1);
                mma_bf16_16x8x16(sc[j], al, bh0, bh1);
            }
        }

        const int r0 = qs + wr + g;
        const int r1 = r0 + 8;
        const bool part = (ks + 63 > qs + wr);
        #pragma unroll
        for (int j = 0; j < 8; j++) {
            int cb = ks + j * 8 + 2 * tg;
            sc[j][0] = (part && cb     > r0) ? -1e30f : sc[j][0] * scale;
            sc[j][1] = (part && cb + 1 > r0) ? -1e30f : sc[j][1] * scale;
            sc[j][2] = (part && cb     > r1) ? -1e30f : sc[j][2] * scale;
            sc[j][3] = (part && cb + 1 > r1) ? -1e30f : sc[j][3] * scale;
        }

        float mx0 = -INFINITY, mx1 = -INFINITY;
        #pragma unroll
        for (int j = 0; j < 8; j++) {
            mx0 = fmaxf(mx0, fmaxf(sc[j][0], sc[j][1]));
            mx1 = fmaxf(mx1, fmaxf(sc[j][2], sc[j][3]));
        }
        mx0 = fmaxf(mx0, __shfl_xor_sync(0xffffffff, mx0, 1));
        mx0 = fmaxf(mx0, __shfl_xor_sync(0xffffffff, mx0, 2));
        mx1 = fmaxf(mx1, __shfl_xor_sync(0xffffffff, mx1, 1));
        mx1 = fmaxf(mx1, __shfl_xor_sync(0xffffffff, mx1, 2));

        float nm0 = fmaxf(m0, mx0);
        float nm1 = fmaxf(m1, mx1);
        float fac0 = __expf(m0 - nm0);
        float fac1 = __expf(m1 - nm1);
        m0 = nm0; m1 = nm1;

        float sum0 = 0.f, sum1 = 0.f;
        #pragma unroll
        for (int j = 0; j < 8; j++) {
            sc[j][0] = __expf(sc[j][0] - m0); sum0 += sc[j][0];
            sc[j][1] = __expf(sc[j][1] - m0); sum0 += sc[j][1];
            sc[j][2] = __expf(sc[j][2] - m1); sum1 += sc[j][2];
            sc[j][3] = __expf(sc[j][3] - m1); sum1 += sc[j][3];
        }
        sum0 += __shfl_xor_sync(0xffffffff, sum0, 1);
        sum0 += __shfl_xor_sync(0xffffffff, sum0, 2);
        sum1 += __shfl_xor_sync(0xffffffff, sum1, 1);
        sum1 += __shfl_xor_sync(0xffffffff, sum1, 2);
        l0s = l0s * fac0 + sum0;
        l1s = l1s * fac1 + sum1;

        #pragma unroll
        for (int j = 0; j < 16; j++) {
            o[j][0] *= fac0; o[j][1] *= fac0;
            o[j][2] *= fac1; o[j][3] *= fac1;
        }

        #pragma unroll
        for (int k2 = 0; k2 < 4; k2++) {
            uint32_t ah[4], al[4];
            split_bf2(sc[2*k2  ][0], sc[2*k2  ][1], ah[0], al[0]);
            split_bf2(sc[2*k2  ][2], sc[2*k2  ][3], ah[1], al[1]);
            split_bf2(sc[2*k2+1][0], sc[2*k2+1][1], ah[2], al[2]);
            split_bf2(sc[2*k2+1][2], sc[2*k2+1][3], ah[3], al[3]);
            #pragma unroll
            for (int jd = 0; jd < 16; jd++) {
                const int rb = (jd * 8 + g) * 36 + k2 * 8;
                uint32_t bh0 = Vhi[rb + tg], bh1 = Vhi[rb + tg + 4];
                uint32_t bl0 = Vlo[rb + tg], bl1 = Vlo[rb + tg + 4];
                mma_bf16_16x8x16(o[jd], ah, bh0, bh1);
                mma_bf16_16x8x16(o[jd], ah, bl0, bl1);
                mma_bf16_16x8x16(o[jd], al, bh0, bh1);
            }
        }

        __syncthreads();
        issueKV(kt + 2);
        cp_commit();
    }

    // ---- epilogue: ctx -> g_cp (tf32 bits, A-fragment-permuted) ----
    const float inv0 = 1.f / l0s;
    const float inv1 = 1.f / l1s;
    const int b = bh >> 4;
    const int h = bh & 15;
    const int m_blk = (b * SEQ + qs + wr) >> 4;
    const int lane0 = 4 * g + (tg & 1) * 2;
    const int w0 = (tg >> 1) * 2;
    #pragma unroll
    for (int jd = 0; jd < 16; jd++) {
        int kblk = h * 16 + jd;
        uint32_t* p = g_cp + (((size_t)m_blk * KBLKS + kblk) * 32 + lane0) * 4 + w0;
        *(uint2*)p       = make_uint2(f32_to_tf32(o[jd][0] * inv0), f32_to_tf32(o[jd][2] * inv1));
        *(uint2*)(p + 4) = make_uint2(f32_to_tf32(o[jd][1] * inv0), f32_to_tf32(o[jd][3] * inv1));
    }
}

// ---------------------------------------------------------------------------
extern "C" void kernel_launch(void* const* d_in, const int* in_sizes, int n_in,
                              void* d_out, int out_size)
{
    const float* x     = (const float*)d_in[0];
    const float* Wq    = (const float*)d_in[1];
    const float* Wk    = (const float*)d_in[2];
    const float* Wv    = (const float*)d_in[3];
    const float* Wo    = (const float*)d_in[4];
    const float* bo    = (const float*)d_in[5];
    const float* theta = (const float*)d_in[6];
    float* out = (float*)d_out;

    // 0. Convert + permute x and weights to tf32 fragment layout
    const size_t total_chunks = XCHUNKS + 4 * WCHUNKS;
    cvt_perm_kernel<<<(unsigned)(total_chunks / 256), 256>>>(x, Wq, Wk, Wv, Wo);

    // 1. QKV projections, scatter to [b,h,t,dh]
    cudaFuncSetAttribute(gemm_perm_kernel<0>, cudaFuncAttributeMaxDynamicSharedMemorySize, GEMM_SMEM);
    gemm_perm_kernel<0><<<dim3(DMODEL/256, NROWS/128, 3), 256, GEMM_SMEM>>>(nullptr, nullptr);

    // 2. RoPE -> pre-split bf16 q/k;  V transpose + split
    rope_split_kernel<<<dim3(SEQ/4, BSZ*NHEADS, 2), dim3(64, 4)>>>(theta);
    v_prep_kernel<<<dim3(SEQ/128, HDIM/32, BSZ*NHEADS), 256>>>();

    // 3. Causal flash attention (bf16x3, cp.async double-buffered)
    cudaFuncSetAttribute(attn_bf16_kernel, cudaFuncAttributeMaxDynamicSharedMemorySize, ATTN_SMEM_BYTES);
    attn_bf16_kernel<<<dim3(SEQ/128, BSZ*NHEADS), 256, ATTN_SMEM_BYTES>>>();

    // 4. Output projection + bias
    cudaFuncSetAttribute(gemm_perm_kernel<1>, cudaFuncAttributeMaxDynamicSharedMemorySize, GEMM_SMEM);
    gemm_perm_kernel<1><<<dim3(DMODEL/256, NROWS/128, 1), 256, GEMM_SMEM>>>(bo, out);
}

// round 9
// speedup vs baseline: 5.4784x; 1.1456x over previous
#include <cuda_runtime.h>
#include <cuda_bf16.h>
#include <math.h>
#include <stdint.h>

#define BSZ 2
#define SEQ 2048
#define DMODEL 2048
#define NHEADS 16
#define HDIM 128
#define NROWS (BSZ*SEQ)     // 4096
#define WSZ (DMODEL*DMODEL)
#define KBLKS (DMODEL/8)    // 256 k8-blocks per row
#define NB2T (DMODEL/16)    // 128 n16-blocks

// Scratch (allocation-free rule: __device__ globals)
__device__ float    g_q[BSZ*NHEADS*SEQ*HDIM];
__device__ float    g_k[BSZ*NHEADS*SEQ*HDIM];
__device__ float    g_v[BSZ*NHEADS*SEQ*HDIM];
__device__ uint32_t g_xp[(size_t)NROWS*DMODEL];   // x, tf32 bits, A-fragment-permuted
__device__ uint32_t g_wp[(size_t)4*WSZ];          // Wq,Wk,Wv,Wo tf32 bits, B-fragment-permuted
__device__ uint32_t g_cp[(size_t)NROWS*DMODEL];   // ctx, tf32 bits, A-fragment-permuted
// attention operands, pre-split bf16 hi/lo packed words
__device__ uint32_t g_qh[(size_t)BSZ*NHEADS*SEQ*64];
__device__ uint32_t g_ql[(size_t)BSZ*NHEADS*SEQ*64];
__device__ uint32_t g_kh[(size_t)BSZ*NHEADS*SEQ*64];
__device__ uint32_t g_kl[(size_t)BSZ*NHEADS*SEQ*64];
__device__ uint32_t g_vth[(size_t)BSZ*NHEADS*HDIM*(SEQ/2)];   // [bh][d][tpair]
__device__ uint32_t g_vtl[(size_t)BSZ*NHEADS*HDIM*(SEQ/2)];

// ---------------------------------------------------------------------------
// helpers
// ---------------------------------------------------------------------------
__device__ __forceinline__ uint32_t f32_to_tf32(float f) {
    uint32_t r;
    asm("cvt.rna.tf32.f32 %0, %1;" : "=r"(r) : "f"(f));
    return r;
}

__device__ __forceinline__ void mma_tf32_16x8x8(float c[4], const uint32_t a[4], uint32_t b0, uint32_t b1) {
    asm volatile(
        "mma.sync.aligned.m16n8k8.row.col.f32.tf32.tf32.f32 "
        "{%0,%1,%2,%3}, {%4,%5,%6,%7}, {%8,%9}, {%0,%1,%2,%3};"
        : "+f"(c[0]), "+f"(c[1]), "+f"(c[2]), "+f"(c[3])
        : "r"(a[0]), "r"(a[1]), "r"(a[2]), "r"(a[3]), "r"(b0), "r"(b1));
}

__device__ __forceinline__ void mma_bf16_16x8x16(float c[4], const uint32_t a[4], uint32_t b0, uint32_t b1) {
    asm volatile(
        "mma.sync.aligned.m16n8k16.row.col.f32.bf16.bf16.f32 "
        "{%0,%1,%2,%3}, {%4,%5,%6,%7}, {%8,%9}, {%0,%1,%2,%3};"
        : "+f"(c[0]), "+f"(c[1]), "+f"(c[2]), "+f"(c[3])
        : "r"(a[0]), "r"(a[1]), "r"(a[2]), "r"(a[3]), "r"(b0), "r"(b1));
}

__device__ __forceinline__ uint32_t pack_bf2(float x, float y) {
    __nv_bfloat162 h = __float22bfloat162_rn(make_float2(x, y));
    return *(uint32_t*)&h;
}
__device__ __forceinline__ float bf2_lo_f32(uint32_t w) { return __uint_as_float(w << 16); }
__device__ __forceinline__ float bf2_hi_f32(uint32_t w) { return __uint_as_float(w & 0xffff0000u); }
__device__ __forceinline__ void split_bf2(float x, float y, uint32_t& hi, uint32_t& lo) {
    hi = pack_bf2(x, y);
    lo = pack_bf2(x - bf2_lo_f32(hi), y - bf2_hi_f32(hi));
}

__device__ __forceinline__ void cp16(void* dst, const void* src) {
    uint32_t s = (uint32_t)__cvta_generic_to_shared(dst);
    asm volatile("cp.async.cg.shared.global [%0], [%1], 16;" :: "r"(s), "l"(src));
}
__device__ __forceinline__ void cp_commit() { asm volatile("cp.async.commit_group;"); }
template<int N> __device__ __forceinline__ void cp_wait() { asm volatile("cp.async.wait_group %0;" :: "n"(N)); }

// ---------------------------------------------------------------------------
// Convert + permute x / weights to tf32 fragment layout (unchanged)
// ---------------------------------------------------------------------------
#define XCHUNKS ((size_t)(NROWS/16)*KBLKS*32)   // 2^21
#define WCHUNKS ((size_t)NB2T*KBLKS*32)         // 2^20

__global__ void cvt_perm_kernel(const float* __restrict__ x,
                                const float* __restrict__ Wq,
                                const float* __restrict__ Wk,
                                const float* __restrict__ Wv,
                                const float* __restrict__ Wo)
{
    size_t idx = (size_t)blockIdx.x * 256 + threadIdx.x;
    const int lane = (int)(idx & 31);
    const int g = lane >> 2, tg = lane & 3;
    uint4 o;
    if (idx < XCHUNKS) {
        int kb = (int)((idx >> 5) & (KBLKS - 1));
        int mb = (int)(idx >> 13);
        const float* s = x + (size_t)(mb * 16 + g) * DMODEL + kb * 8 + tg;
        o.x = f32_to_tf32(s[0]);
        o.y = f32_to_tf32(s[8 * DMODEL]);
        o.z = f32_to_tf32(s[4]);
        o.w = f32_to_tf32(s[8 * DMODEL + 4]);
        ((uint4*)g_xp)[idx] = o;
    } else {
        size_t j = idx - XCHUNKS;
        int wsel = (int)(j >> 20);
        size_t o2 = j & ((((size_t)1) << 20) - 1);
        int kb = (int)((o2 >> 5) & (KBLKS - 1));
        int nb2 = (int)(o2 >> 13);
        const float* W = (wsel == 0) ? Wq : (wsel == 1) ? Wk : (wsel == 2) ? Wv : Wo;
        const float* s = W + (size_t)(nb2 * 16 + g) * DMODEL + kb * 8 + tg;
        o.x = f32_to_tf32(s[0]);
        o.y = f32_to_tf32(s[4]);
        o.z = f32_to_tf32(s[8 * DMODEL]);
        o.w = f32_to_tf32(s[8 * DMODEL + 4]);
        ((uint4*)g_wp)[(size_t)wsel * WCHUNKS + o2] = o;
    }
}

// ---------------------------------------------------------------------------
// tf32 NT GEMM on fragment-permuted operands.
// NEW: block tile 128x128, 128 threads = 4 warps (2x2), warp tile 64x64,
// 2-stage cp.async, 3 CTAs/SM target.
// MODE 0: A=g_xp, z selects W, epilogue scatters f32 to g_q/g_k/g_v [b,h,t,dh]
// MODE 1: A=g_cp, W=Wo, adds bias, writes f32 row-major to Cout
// ---------------------------------------------------------------------------
#define ABYTES (8*4*32*16)     // 16384 (A: 8 m16 blocks)
#define BBYTES (8*4*32*16)     // 16384 (B: 8 n16 blocks)
#define STGB   (ABYTES + BBYTES)   // 32768
#define NSTG 2
#define GEMM_SMEM (NSTG * STGB)    // 65536

template<int MODE>
__global__ void __launch_bounds__(128, 3) gemm_perm_kernel(
    const float* __restrict__ bias, float* __restrict__ Cout)
{
    extern __shared__ char sh[];

    const int tid  = threadIdx.x;
    const int lane = tid & 31;
    const int wrp  = tid >> 5;     // 0..3
    const int g    = lane >> 2;
    const int tg   = lane & 3;
    const int rh   = wrp >> 1;     // row-half 0/1 (64 rows each)
    const int cw   = wrp & 1;      // col-half 0/1 (64 cols each)

    const int rowBase = blockIdx.y * 128;
    const int colBase = blockIdx.x * 128;
    const int mb0  = blockIdx.y * 8;    // 8 m16 blocks
    const int nb20 = blockIdx.x * 8;    // 8 n16 blocks

    const uint32_t* Ag = (MODE == 0) ? g_xp : g_cp;
    const uint32_t* Bg = g_wp + (size_t)((MODE == 0) ? blockIdx.z : 3) * WSZ;
    float* dstQKV = nullptr;
    if (MODE == 0)
        dstQKV = (blockIdx.z == 0) ? g_q : (blockIdx.z == 1 ? g_k : g_v);

    auto issue = [&](int kt, int s) {
        char* st = sh + s * STGB;
        const int kb0 = kt * 4;
        #pragma unroll
        for (int p = 0; p < 8; p++) {              // A: 1024 chunks
            int c = tid + p * 128;
            int mbL = c >> 7, kbL = (c >> 5) & 3, ln = c & 31;
            const uint32_t* gsrc = Ag + (((size_t)(mb0 + mbL) * KBLKS + kb0 + kbL) * 32 + ln) * 4;
            cp16(st + c * 16, gsrc);
        }
        #pragma unroll
        for (int p = 0; p < 8; p++) {              // B: 1024 chunks
            int c = tid + p * 128;
            int nbL = c >> 7, kbL = (c >> 5) & 3, ln = c & 31;
            const uint32_t* gsrc = Bg + (((size_t)(nb20 + nbL) * KBLKS + kb0 + kbL) * 32 + ln) * 4;
            cp16(st + ABYTES + c * 16, gsrc);
        }
    };

    float acc[4][8][4];
    #pragma unroll
    for (int i = 0; i < 4; i++)
        #pragma unroll
        for (int j = 0; j < 8; j++)
            #pragma unroll
            for (int c = 0; c < 4; c++) acc[i][j][c] = 0.f;

    issue(0, 0); cp_commit();
    issue(1, 1); cp_commit();

    const int NKT = DMODEL / 32;   // 64
    for (int kt = 0; kt < NKT; kt++) {
        cp_wait<1>();
        __syncthreads();

        const char* st = sh + (kt & 1) * STGB;
        const uint4* As4 = (const uint4*)st;
        const uint4* Bs4 = (const uint4*)(st + ABYTES);

        #pragma unroll
        for (int kk = 0; kk < 4; kk++) {
            uint4 af[4];
            #pragma unroll
            for (int i = 0; i < 4; i++)
                af[i] = As4[((rh * 4 + i) * 4 + kk) * 32 + lane];
            #pragma unroll
            for (int j2 = 0; j2 < 4; j2++) {
                uint4 bv = Bs4[((cw * 4 + j2) * 4 + kk) * 32 + lane];
                #pragma unroll
                for (int i = 0; i < 4; i++) {
                    mma_tf32_16x8x8(acc[i][2*j2  ], (const uint32_t*)&af[i], bv.x, bv.y);
                    mma_tf32_16x8x8(acc[i][2*j2+1], (const uint32_t*)&af[i], bv.z, bv.w);
                }
            }
        }

        __syncthreads();                      // reads done before overwrite
        if (kt + 2 < NKT) issue(kt + 2, kt & 1);
        cp_commit();
    }

    if (MODE == 0) {
        #pragma unroll
        for (int i = 0; i < 4; i++) {
            #pragma unroll
            for (int cc = 0; cc < 2; cc++) {
                int m = rowBase + rh * 64 + i * 16 + g + cc * 8;
                int b = m >> 11;
                int t = m & (SEQ - 1);
                size_t rowoff = ((size_t)(b * NHEADS) * SEQ + t) << 7;
                #pragma unroll
                for (int j = 0; j < 8; j++) {
                    int n0 = colBase + cw * 64 + j * 8 + tg * 2;
                    int h  = n0 >> 7;
                    int dh = n0 & (HDIM - 1);
                    float* dst = dstQKV + rowoff + (((size_t)h * SEQ) << 7) + dh;
                    dst[0] = acc[i][j][cc * 2 + 0];
                    dst[1] = acc[i][j][cc * 2 + 1];
                }
            }
        }
    } else {
        #pragma unroll
        for (int i = 0; i < 4; i++) {
            #pragma unroll
            for (int cc = 0; cc < 2; cc++) {
                int m = rowBase + rh * 64 + i * 16 + g + cc * 8;
                #pragma unroll
                for (int j = 0; j < 8; j++) {
                    int n0 = colBase + cw * 64 + j * 8 + tg * 2;
                    float2 v;
                    v.x = acc[i][j][cc * 2 + 0] + bias[n0];
                    v.y = acc[i][j][cc * 2 + 1] + bias[n0 + 1];
                    *(float2*)(Cout + (size_t)m * DMODEL + n0) = v;
                }
            }
        }
    }
}

// ---------------------------------------------------------------------------
// RoPE -> pre-split bf16 q/k words (unchanged).
// ---------------------------------------------------------------------------
__global__ void rope_split_kernel(const float* __restrict__ theta)
{
    const int j  = threadIdx.x;                    // 0..63
    const int t  = blockIdx.x * 4 + threadIdx.y;
    const int bh = blockIdx.y;
    const bool isK = blockIdx.z != 0;
    const int jj = j & 31;

    const float* row = (isK ? g_k : g_q) + ((size_t)bh * SEQ + t) * HDIM;
    float4 v = *(const float4*)(row + 4 * jj);
    float th0 = theta[2*jj], th1 = theta[2*jj + 1];
    float s0, c0, s1, c1;
    sincosf((float)t * th0, &s0, &c0);
    sincosf((float)t * th1, &s1, &c1);

    float o0, o1;
    if (j < 32) { o0 = v.x * c0 - v.y * s0;  o1 = v.z * c1 - v.w * s1; }
    else        { o0 = v.x * s0 + v.y * c0;  o1 = v.z * s1 + v.w * c1; }

    uint32_t hi, lo;
    split_bf2(o0, o1, hi, lo);
    size_t woff = ((size_t)bh * SEQ + t) * 64 + j;
    (isK ? g_kh : g_qh)[woff] = hi;
    (isK ? g_kl : g_ql)[woff] = lo;
}

// ---------------------------------------------------------------------------
// V prep: transpose + split V once globally (unchanged).
// ---------------------------------------------------------------------------
__global__ void __launch_bounds__(256) v_prep_kernel()
{
    __shared__ float sm[128 * 37];
    const int tid = threadIdx.x;
    const int t0 = blockIdx.x * 128;
    const int d0 = blockIdx.y * 32;
    const int bh = blockIdx.z;
    const float* src = g_v + ((size_t)bh * SEQ + t0) * HDIM + d0;

    #pragma unroll
    for (int p = 0; p < 4; p++) {
        int c = tid + p * 256;
        int t = c >> 3;
        int q = (c & 7) * 4;
        float4 v = *(const float4*)(src + (size_t)t * HDIM + q);
        float* d = sm + t * 37 + q;
        d[0] = v.x; d[1] = v.y; d[2] = v.z; d[3] = v.w;
    }
    __syncthreads();

    uint32_t* dh = g_vth + ((size_t)bh * HDIM + d0) * (SEQ/2) + t0 / 2;
    uint32_t* dl = g_vtl + ((size_t)bh * HDIM + d0) * (SEQ/2) + t0 / 2;
    #pragma unroll
    for (int p = 0; p < 8; p++) {
        int w = tid + p * 256;
        int d = w >> 6;
        int tp = w & 63;
        uint32_t hi, lo;
        split_bf2(sm[(2*tp) * 37 + d], sm[(2*tp + 1) * 37 + d], hi, lo);
        dh[(size_t)d * (SEQ/2) + tp] = hi;
        dl[(size_t)d * (SEQ/2) + tp] = lo;
    }
}

// ---------------------------------------------------------------------------
// Tensor-core flash attention (bf16x3, cp.async double-buffered) — unchanged.
// ---------------------------------------------------------------------------
#define AQHI 0
#define AQLO 8704
#define AST0 17408
#define ASTSZ 17920
#define AKHI 0
#define AKLO 4352
#define AVHI 8704
#define AVLO 13312
#define ATTN_SMEM_BYTES ((AST0 + 2*ASTSZ) * 4)

__global__ void __launch_bounds__(256, 1) attn_bf16_kernel()
{
    extern __shared__ uint32_t sm[];

    const int tid  = threadIdx.x;
    const int lane = tid & 31;
    const int wrp  = tid >> 5;
    const int g    = lane >> 2;
    const int tg   = lane & 3;
    const int wr   = wrp * 16;

    const int qt = gridDim.x - 1 - blockIdx.x;   // big tiles first
    const int bh = blockIdx.y;
    const int qs = qt * 128;
    const size_t wbase = (size_t)bh * SEQ * 64;
    const size_t vbase = (size_t)bh * HDIM * (SEQ/2);
    const float scale = 0.08838834764831845f;
    const int ktiles = 2 * qt + 2;

    auto issueKV = [&](int kt) {
        if (kt >= ktiles) return;
        uint32_t* st = sm + AST0 + (kt & 1) * ASTSZ;
        const int ks = kt * 64;
        #pragma unroll
        for (int p = 0; p < 4; p++) {
            int c = tid + p * 256;
            int r = c >> 4, q4 = (c & 15) * 4;
            cp16(st + AKHI + r * 68 + q4, g_kh + wbase + (size_t)(ks + r) * 64 + q4);
            cp16(st + AKLO + r * 68 + q4, g_kl + wbase + (size_t)(ks + r) * 64 + q4);
        }
        #pragma unroll
        for (int p = 0; p < 4; p++) {
            int c = tid + p * 256;
            int d = c >> 3, q4 = (c & 7) * 4;
            cp16(st + AVHI + d * 36 + q4, g_vth + vbase + (size_t)d * (SEQ/2) + kt * 32 + q4);
            cp16(st + AVLO + d * 36 + q4, g_vtl + vbase + (size_t)d * (SEQ/2) + kt * 32 + q4);
        }
    };

    #pragma unroll
    for (int p = 0; p < 8; p++) {
        int c = tid + p * 256;
        int r = c >> 4, q4 = (c & 15) * 4;
        cp16(sm + AQHI + r * 68 + q4, g_qh + wbase + (size_t)(qs + r) * 64 + q4);
        cp16(sm + AQLO + r * 68 + q4, g_ql + wbase + (size_t)(qs + r) * 64 + q4);
    }
    issueKV(0); cp_commit();
    issueKV(1); cp_commit();

    float o[16][4];
    #pragma unroll
    for (int j = 0; j < 16; j++)
        #pragma unroll
        for (int c = 0; c < 4; c++) o[j][c] = 0.f;
    float m0 = -INFINITY, m1 = -INFINITY, l0s = 0.f, l1s = 0.f;

    for (int kt = 0; kt < ktiles; kt++) {
        const int ks = kt * 64;
        cp_wait<1>();
        __syncthreads();

        const uint32_t* Khi = sm + AST0 + (kt & 1) * ASTSZ + AKHI;
        const uint32_t* Klo = sm + AST0 + (kt & 1) * ASTSZ + AKLO;
        const uint32_t* Vhi = sm + AST0 + (kt & 1) * ASTSZ + AVHI;
        const uint32_t* Vlo = sm + AST0 + (kt & 1) * ASTSZ + AVLO;
        const uint32_t* Qhi = sm + AQHI;
        const uint32_t* Qlo = sm + AQLO;

        float sc[8][4];
        #pragma unroll
        for (int j = 0; j < 8; j++)
            #pragma unroll
            for (int c = 0; c < 4; c++) sc[j][c] = 0.f;

        const int ra0 = (wr + g) * 68;
        const int ra1 = (wr + g + 8) * 68;
        #pragma unroll
        for (int kk = 0; kk < 8; kk++) {
            const int kw = kk * 8;
            uint32_t ah[4], al[4];
            ah[0] = Qhi[ra0 + kw + tg];     al[0] = Qlo[ra0 + kw + tg];
            ah[1] = Qhi[ra1 + kw + tg];     al[1] = Qlo[ra1 + kw + tg];
            ah[2] = Qhi[ra0 + kw + tg + 4]; al[2] = Qlo[ra0 + kw + tg + 4];
            ah[3] = Qhi[ra1 + kw + tg + 4]; al[3] = Qlo[ra1 + kw + tg + 4];
            #pragma unroll
            for (int j = 0; j < 8; j++) {
                const int rb = (j * 8 + g) * 68 + kw;
                uint32_t bh0 = Khi[rb + tg], bh1 = Khi[rb + tg + 4];
                uint32_t bl0 = Klo[rb + tg], bl1 = Klo[rb + tg + 4];
                mma_bf16_16x8x16(sc[j], ah, bh0, bh1);
                mma_bf16_16x8x16(sc[j], ah, bl0, bl1);
                mma_bf16_16x8x16(sc[j], al, bh0, bh1);
            }
        }

        const int r0 = qs + wr + g;
        const int r1 = r0 + 8;
        const bool part = (ks + 63 > qs + wr);
        #pragma unroll
        for (int j = 0; j < 8; j++) {
            int cb = ks + j * 8 + 2 * tg;
            sc[j][0] = (part && cb     > r0) ? -1e30f : sc[j][0] * scale;
            sc[j][1] = (part && cb + 1 > r0) ? -1e30f : sc[j][1] * scale;
            sc[j][2] = (part && cb     > r1) ? -1e30f : sc[j][2] * scale;
            sc[j][3] = (part && cb + 1 > r1) ? -1e30f : sc[j][3] * scale;
        }

        float mx0 = -INFINITY, mx1 = -INFINITY;
        #pragma unroll
        for (int j = 0; j < 8; j++) {
            mx0 = fmaxf(mx0, fmaxf(sc[j][0], sc[j][1]));
            mx1 = fmaxf(mx1, fmaxf(sc[j][2], sc[j][3]));
        }
        mx0 = fmaxf(mx0, __shfl_xor_sync(0xffffffff, mx0, 1));
        mx0 = fmaxf(mx0, __shfl_xor_sync(0xffffffff, mx0, 2));
        mx1 = fmaxf(mx1, __shfl_xor_sync(0xffffffff, mx1, 1));
        mx1 = fmaxf(mx1, __shfl_xor_sync(0xffffffff, mx1, 2));

        float nm0 = fmaxf(m0, mx0);
        float nm1 = fmaxf(m1, mx1);
        float fac0 = __expf(m0 - nm0);
        float fac1 = __expf(m1 - nm1);
        m0 = nm0; m1 = nm1;

        float sum0 = 0.f, sum1 = 0.f;
        #pragma unroll
        for (int j = 0; j < 8; j++) {
            sc[j][0] = __expf(sc[j][0] - m0); sum0 += sc[j][0];
            sc[j][1] = __expf(sc[j][1] - m0); sum0 += sc[j][1];
            sc[j][2] = __expf(sc[j][2] - m1); sum1 += sc[j][2];
            sc[j][3] = __expf(sc[j][3] - m1); sum1 += sc[j][3];
        }
        sum0 += __shfl_xor_sync(0xffffffff, sum0, 1);
        sum0 += __shfl_xor_sync(0xffffffff, sum0, 2);
        sum1 += __shfl_xor_sync(0xffffffff, sum1, 1);
        sum1 += __shfl_xor_sync(0xffffffff, sum1, 2);
        l0s = l0s * fac0 + sum0;
        l1s = l1s * fac1 + sum1;

        #pragma unroll
        for (int j = 0; j < 16; j++) {
            o[j][0] *= fac0; o[j][1] *= fac0;
            o[j][2] *= fac1; o[j][3] *= fac1;
        }

        #pragma unroll
        for (int k2 = 0; k2 < 4; k2++) {
            uint32_t ah[4], al[4];
            split_bf2(sc[2*k2  ][0], sc[2*k2  ][1], ah[0], al[0]);
            split_bf2(sc[2*k2  ][2], sc[2*k2  ][3], ah[1], al[1]);
            split_bf2(sc[2*k2+1][0], sc[2*k2+1][1], ah[2], al[2]);
            split_bf2(sc[2*k2+1][2], sc[2*k2+1][3], ah[3], al[3]);
            #pragma unroll
            for (int jd = 0; jd < 16; jd++) {
                const int rb = (jd * 8 + g) * 36 + k2 * 8;
                uint32_t bh0 = Vhi[rb + tg], bh1 = Vhi[rb + tg + 4];
                uint32_t bl0 = Vlo[rb + tg], bl1 = Vlo[rb + tg + 4];
                mma_bf16_16x8x16(o[jd], ah, bh0, bh1);
                mma_bf16_16x8x16(o[jd], ah, bl0, bl1);
                mma_bf16_16x8x16(o[jd], al, bh0, bh1);
            }
        }

        __syncthreads();
        issueKV(kt + 2);
        cp_commit();
    }

    // ---- epilogue: ctx -> g_cp (tf32 bits, A-fragment-permuted) ----
    const float inv0 = 1.f / l0s;
    const float inv1 = 1.f / l1s;
    const int b = bh >> 4;
    const int h = bh & 15;
    const int m_blk = (b * SEQ + qs + wr) >> 4;
    const int lane0 = 4 * g + (tg & 1) * 2;
    const int w0 = (tg >> 1) * 2;
    #pragma unroll
    for (int jd = 0; jd < 16; jd++) {
        int kblk = h * 16 + jd;
        uint32_t* p = g_cp + (((size_t)m_blk * KBLKS + kblk) * 32 + lane0) * 4 + w0;
        *(uint2*)p       = make_uint2(f32_to_tf32(o[jd][0] * inv0), f32_to_tf32(o[jd][2] * inv1));
        *(uint2*)(p + 4) = make_uint2(f32_to_tf32(o[jd][1] * inv0), f32_to_tf32(o[jd][3] * inv1));
    }
}

// ---------------------------------------------------------------------------
extern "C" void kernel_launch(void* const* d_in, const int* in_sizes, int n_in,
                              void* d_out, int out_size)
{
    const float* x     = (const float*)d_in[0];
    const float* Wq    = (const float*)d_in[1];
    const float* Wk    = (const float*)d_in[2];
    const float* Wv    = (const float*)d_in[3];
    const float* Wo    = (const float*)d_in[4];
    const float* bo    = (const float*)d_in[5];
    const float* theta = (const float*)d_in[6];
    float* out = (float*)d_out;

    // 0. Convert + permute x and weights to tf32 fragment layout
    const size_t total_chunks = XCHUNKS + 4 * WCHUNKS;
    cvt_perm_kernel<<<(unsigned)(total_chunks / 256), 256>>>(x, Wq, Wk, Wv, Wo);

    // 1. QKV projections (128x128 tiles, 3 CTAs/SM), scatter to [b,h,t,dh]
    cudaFuncSetAttribute(gemm_perm_kernel<0>, cudaFuncAttributeMaxDynamicSharedMemorySize, GEMM_SMEM);
    gemm_perm_kernel<0><<<dim3(DMODEL/128, NROWS/128, 3), 128, GEMM_SMEM>>>(nullptr, nullptr);

    // 2. RoPE -> pre-split bf16 q/k;  V transpose + split
    rope_split_kernel<<<dim3(SEQ/4, BSZ*NHEADS, 2), dim3(64, 4)>>>(theta);
    v_prep_kernel<<<dim3(SEQ/128, HDIM/32, BSZ*NHEADS), 256>>>();

    // 3. Causal flash attention (bf16x3, cp.async double-buffered)
    cudaFuncSetAttribute(attn_bf16_kernel, cudaFuncAttributeMaxDynamicSharedMemorySize, ATTN_SMEM_BYTES);
    attn_bf16_kernel<<<dim3(SEQ/128, BSZ*NHEADS), 256, ATTN_SMEM_BYTES>>>();

    // 4. Output projection + bias
    cudaFuncSetAttribute(gemm_perm_kernel<1>, cudaFuncAttributeMaxDynamicSharedMemorySize, GEMM_SMEM);
    gemm_perm_kernel<1><<<dim3(DMODEL/128, NROWS/128, 1), 128, GEMM_SMEM>>>(bo, out);
}